// round 12
// baseline (speedup 1.0000x reference)
#include <cuda_runtime.h>
#include <cuda_bf16.h>
#include <math.h>
#include <stdint.h>

// Problem constants
constexpr int cB = 16;
constexpr int cN = 32;
constexpr int cX = 36;
constexpr int cD = 2048;
constexpr int cH = 512;
constexpr int ROWS = cB * cN;     // 512
constexpr int K2 = 2 * cD;        // 4096
constexpr int MLP_SPLIT = 16;
constexpr int INN_SPLIT = 4;
constexpr int FT_SPLIT = 32;
#define BIG_NEG_F (-1000000000.0f)

// ---------------- scratch ----------------
__device__ __nv_bfloat16 g_fdh[ROWS * cD], g_fdl[ROWS * cD];
__device__ __nv_bfloat16 g_X2h[ROWS * K2], g_X2l[ROWS * K2];
__device__ __nv_bfloat16 g_Wt1h[cH * cD], g_Wt1l[cH * cD];
__device__ __nv_bfloat16 g_Wt2h[cH * K2], g_Wt2l[cH * K2];
__device__ float g_Hb[FT_SPLIT * cB * cH];
__device__ float g_Hbs[cB * cH];
__device__ float g_Hpart[MLP_SPLIT * ROWS * cH];
__device__ float g_tproj[cB * cX * cD];
__device__ float g_tprojP[2 * cB * cX * cD];
__device__ float g_inners[INN_SPLIT * cB * cN * cX * 64];
__device__ float g_scores[ROWS];
__device__ int g_flag;   // 0 = Wbil identity, 1 = general

// ---------------- helpers ----------------
__device__ __forceinline__ uint32_t smem_u32(const void* p) {
    uint32_t a;
    asm("{ .reg .u64 t; cvta.to.shared.u64 t, %1; cvt.u32.u64 %0, t; }" : "=r"(a) : "l"(p));
    return a;
}
__device__ __forceinline__ void ldsm4(uint32_t* r, uint32_t addr) {
    asm volatile("ldmatrix.sync.aligned.m8n8.x4.shared.b16 {%0,%1,%2,%3}, [%4];"
                 : "=r"(r[0]), "=r"(r[1]), "=r"(r[2]), "=r"(r[3]) : "r"(addr));
}
__device__ __forceinline__ void mma_bf16(float* c, const uint32_t* a, uint32_t b0, uint32_t b1) {
    asm volatile("mma.sync.aligned.m16n8k16.row.col.f32.bf16.bf16.f32 "
                 "{%0,%1,%2,%3}, {%4,%5,%6,%7}, {%8,%9}, {%0,%1,%2,%3};"
                 : "+f"(c[0]), "+f"(c[1]), "+f"(c[2]), "+f"(c[3])
                 : "r"(a[0]), "r"(a[1]), "r"(a[2]), "r"(a[3]), "r"(b0), "r"(b1));
}
__device__ __forceinline__ void cvt_hl4(float4 v, uint2& hv, uint2& lv) {
    __nv_bfloat16 hx = __float2bfloat16(v.x), hy = __float2bfloat16(v.y);
    __nv_bfloat16 hz = __float2bfloat16(v.z), hw = __float2bfloat16(v.w);
    __nv_bfloat16 lx = __float2bfloat16(v.x - __bfloat162float(hx));
    __nv_bfloat16 ly = __float2bfloat16(v.y - __bfloat162float(hy));
    __nv_bfloat16 lz = __float2bfloat16(v.z - __bfloat162float(hz));
    __nv_bfloat16 lw = __float2bfloat16(v.w - __bfloat162float(hw));
    hv.x = ((uint32_t)__bfloat16_as_ushort(hy) << 16) | __bfloat16_as_ushort(hx);
    hv.y = ((uint32_t)__bfloat16_as_ushort(hw) << 16) | __bfloat16_as_ushort(hz);
    lv.x = ((uint32_t)__bfloat16_as_ushort(ly) << 16) | __bfloat16_as_ushort(lx);
    lv.y = ((uint32_t)__bfloat16_as_ushort(lw) << 16) | __bfloat16_as_ushort(lz);
}

// SMEM element-offset layout per buffer (bf16 units). Row stride 24 elements.
constexpr int sAH = 0;              // [2][128][24]
constexpr int sAL = 6144;
constexpr int sBH = 12288;          // [2][64][24]
constexpr int sBL = 15360;
constexpr int SM_ELEMS = 18432;
constexpr int SMEM_BYTES = 2 * SM_ELEMS * 2;   // 73,728 B

// ======== compute phase: one 32-K chunk from a buffer ========
__device__ __forceinline__ void compute_chunk(uint32_t cb, int mrow, int nrow, int g, int r8,
                                              float acc[2][4][4]) {
#pragma unroll
    for (int ks = 0; ks < 2; ks++) {
        uint32_t ah[2][4], al[2][4], bh[2][4], bl[2][4];
#pragma unroll
        for (int mt = 0; mt < 2; mt++) {
            int row = mrow + mt * 16 + (g & 1) * 8 + r8;
            uint32_t bo = (uint32_t)(((ks * 128 + row) * 24 + (g >> 1) * 8) * 2);
            ldsm4(ah[mt], cb + sAH * 2 + bo);
            ldsm4(al[mt], cb + sAL * 2 + bo);
        }
#pragma unroll
        for (int bt = 0; bt < 2; bt++) {
            int row = nrow + bt * 16 + (g >> 1) * 8 + r8;
            uint32_t bo = (uint32_t)(((ks * 64 + row) * 24 + (g & 1) * 8) * 2);
            ldsm4(bh[bt], cb + sBH * 2 + bo);
            ldsm4(bl[bt], cb + sBL * 2 + bo);
        }
#pragma unroll
        for (int mi = 0; mi < 2; mi++)
#pragma unroll
            for (int nj = 0; nj < 4; nj++) {
                int bt = nj >> 1, sub = (nj & 1) * 2;
                mma_bf16(acc[mi][nj], ah[mi], bh[bt][sub], bh[bt][sub + 1]);
                mma_bf16(acc[mi][nj], ah[mi], bl[bt][sub], bl[bt][sub + 1]);
                mma_bf16(acc[mi][nj], al[mi], bh[bt][sub], bh[bt][sub + 1]);
            }
    }
}

// ============ bf16-split HMMA GEMM: AM/BM modes, 2-stage register pipeline ============
// AM: 0 = gA fp32 [M,K], convert in-loop. 1 = gAh/gAl bf16 [M,K] pre-split.
// BM: 0 = gB fp32 [K,N] (NN transpose in STS). 1 = gBh/gBl bf16 [N,K] pre-split.
//     2 = fp32 [N,K] (NT) with row clamp to Bn; source = gB2 if g_flag==0 else gB.
template <int AM, int BM>
__global__ __launch_bounds__(256, 2)
void hgemm(const float* __restrict__ gA,
           const __nv_bfloat16* __restrict__ gAh, const __nv_bfloat16* __restrict__ gAl,
           const float* __restrict__ gB, const float* __restrict__ gB2,
           const __nv_bfloat16* __restrict__ gBh, const __nv_bfloat16* __restrict__ gBl,
           float* __restrict__ gC,
           int M, int Nld, int Kchunks, int lda, int ldb, int Bn, int nsplit, int onlyFallback,
           long sAb, long sBb, long sCb, long sAk, long sBk, long sCk) {
    if (onlyFallback && g_flag == 0) return;
    extern __shared__ __align__(16) uint16_t sm[];
    const int zb = blockIdx.z / nsplit;
    const int zs = blockIdx.z - zb * nsplit;
    if (AM == 0) gA += (long)zb * sAb + (long)zs * sAk;
    else { gAh += (long)zb * sAb + (long)zs * sAk; gAl += (long)zb * sAb + (long)zs * sAk; }
    if (BM == 1) { gBh += (long)zb * sBb + (long)zs * sBk; gBl += (long)zb * sBb + (long)zs * sBk; }
    else if (BM == 0) gB += (long)zb * sBb + (long)zs * sBk;
    else {
        const float* src = (g_flag == 0) ? gB2 : gB;
        gB = src + (long)zb * sBb + (long)zs * sBk;
    }
    gC += (long)zb * sCb + (long)zs * sCk;
    const int m0 = blockIdx.y * 128;
    const int n0 = blockIdx.x * 64;
    const int tid = threadIdx.x;
    const int lane = tid & 31;
    const int w = tid >> 5;
    const int mrow = (w & 3) * 32;
    const int nrow = (w >> 2) * 32;
    const uint32_t sbase = smem_u32(sm);

    float4 ra[4];
    uint4 pah[2], pal[2];
    float4 rbf[2];
    uint4 pbh, pbl;

    int a_r[4], a_j[4];
    if (AM == 0) {
#pragma unroll
        for (int it = 0; it < 4; it++) { int f = it * 256 + tid; a_r[it] = f >> 3; a_j[it] = f & 7; }
    } else {
#pragma unroll
        for (int it = 0; it < 2; it++) { int f = it * 256 + tid; a_r[it] = f >> 2; a_j[it] = f & 3; }
    }
    int b_r[2], b_j[2];
    if (BM == 0) {
#pragma unroll
        for (int it = 0; it < 2; it++) { int f = it * 256 + tid; b_r[it] = f >> 4; b_j[it] = f & 15; }
    } else if (BM == 2) {
#pragma unroll
        for (int it = 0; it < 2; it++) { int f = it * 256 + tid; b_r[it] = f >> 3; b_j[it] = f & 7; }
    } else {
        b_r[0] = tid >> 2; b_j[0] = tid & 3;
    }

    auto loadA = [&](int k0) {
        if (AM == 0) {
#pragma unroll
            for (int it = 0; it < 4; it++) {
                ra[it] = make_float4(0.f, 0.f, 0.f, 0.f);
                if (m0 + a_r[it] < M)
                    ra[it] = *(const float4*)(gA + (long)(m0 + a_r[it]) * lda + k0 + a_j[it] * 4);
            }
        } else {
#pragma unroll
            for (int it = 0; it < 2; it++) {
                pah[it] = make_uint4(0, 0, 0, 0); pal[it] = make_uint4(0, 0, 0, 0);
                if (m0 + a_r[it] < M) {
                    long base = (long)(m0 + a_r[it]) * lda + k0 + a_j[it] * 8;
                    pah[it] = *(const uint4*)(gAh + base);
                    pal[it] = *(const uint4*)(gAl + base);
                }
            }
        }
    };
    auto loadB = [&](int k0) {
        if (BM == 0) {
#pragma unroll
            for (int it = 0; it < 2; it++)
                rbf[it] = *(const float4*)(gB + (long)(k0 + b_r[it]) * ldb + n0 + b_j[it] * 4);
        } else if (BM == 2) {
#pragma unroll
            for (int it = 0; it < 2; it++) {
                int rr = min(n0 + b_r[it], Bn - 1);
                rbf[it] = *(const float4*)(gB + (long)rr * ldb + k0 + b_j[it] * 4);
            }
        } else {
            long base = (long)(n0 + b_r[0]) * ldb + k0 + b_j[0] * 8;
            pbh = *(const uint4*)(gBh + base);
            pbl = *(const uint4*)(gBl + base);
        }
    };
    auto storeA = [&](uint16_t* bp) {
        if (AM == 0) {
#pragma unroll
            for (int it = 0; it < 4; it++) {
                uint2 hv, lv;
                cvt_hl4(ra[it], hv, lv);
                int off = (((a_j[it] >> 2) * 128 + a_r[it]) * 24) + (a_j[it] & 3) * 4;
                *(uint2*)&bp[sAH + off] = hv;
                *(uint2*)&bp[sAL + off] = lv;
            }
        } else {
#pragma unroll
            for (int it = 0; it < 2; it++) {
                int off = (((a_j[it] >> 1) * 128 + a_r[it]) * 24) + (a_j[it] & 1) * 8;
                *(uint4*)&bp[sAH + off] = pah[it];
                *(uint4*)&bp[sAL + off] = pal[it];
            }
        }
    };
    auto storeB = [&](uint16_t* bp) {
        if (BM == 0) {
#pragma unroll
            for (int it = 0; it < 2; it++) {
                float vv[4] = {rbf[it].x, rbf[it].y, rbf[it].z, rbf[it].w};
                int h = b_r[it] >> 4, kk = b_r[it] & 15;
#pragma unroll
                for (int e = 0; e < 4; e++) {
                    int n = b_j[it] * 4 + e;
                    __nv_bfloat16 hb = __float2bfloat16(vv[e]);
                    __nv_bfloat16 lb = __float2bfloat16(vv[e] - __bfloat162float(hb));
                    int off = ((h * 64 + n) * 24) + kk;
                    bp[sBH + off] = __bfloat16_as_ushort(hb);
                    bp[sBL + off] = __bfloat16_as_ushort(lb);
                }
            }
        } else if (BM == 2) {
#pragma unroll
            for (int it = 0; it < 2; it++) {
                uint2 hv, lv;
                cvt_hl4(rbf[it], hv, lv);
                int off = (((b_j[it] >> 2) * 64 + b_r[it]) * 24) + (b_j[it] & 3) * 4;
                *(uint2*)&bp[sBH + off] = hv;
                *(uint2*)&bp[sBL + off] = lv;
            }
        } else {
            int off = (((b_j[0] >> 1) * 64 + b_r[0]) * 24) + (b_j[0] & 1) * 8;
            *(uint4*)&bp[sBH + off] = pbh;
            *(uint4*)&bp[sBL + off] = pbl;
        }
    };

    float acc[2][4][4];
#pragma unroll
    for (int i = 0; i < 2; i++)
#pragma unroll
        for (int j = 0; j < 4; j++)
#pragma unroll
            for (int q = 0; q < 4; q++) acc[i][j][q] = 0.f;

    const int g = lane >> 3, r8 = lane & 7;

    loadA(0); loadB(0);
    storeA(sm); storeB(sm);
    __syncthreads();
    if (Kchunks > 1) { loadA(32); loadB(32); }

    for (int c = 0; c < Kchunks; c++) {
        if (c + 1 < Kchunks) {
            uint16_t* bp = sm + ((c + 1) & 1) * SM_ELEMS;
            storeA(bp); storeB(bp);
        }
        if (c + 2 < Kchunks) { loadA((c + 2) * 32); loadB((c + 2) * 32); }
        compute_chunk(sbase + (uint32_t)((c & 1) * SM_ELEMS * 2), mrow, nrow, g, r8, acc);
        __syncthreads();
    }

#pragma unroll
    for (int mi = 0; mi < 2; mi++) {
        int rg = m0 + mrow + mi * 16 + (lane >> 2);
#pragma unroll
        for (int nj = 0; nj < 4; nj++) {
            int cg = n0 + nrow + nj * 8 + 2 * (lane & 3);
            if (rg < M) {
                *(float2*)(gC + (long)rg * Nld + cg) = make_float2(acc[mi][nj][0], acc[mi][nj][1]);
            }
            if (rg + 8 < M) {
                *(float2*)(gC + (long)(rg + 8) * Nld + cg) = make_float2(acc[mi][nj][2], acc[mi][nj][3]);
            }
        }
    }
}

// ---------------- flag init + identity check ----------------
__global__ void init_flag_kernel() { g_flag = 0; }

__global__ void check_identity(const float* __restrict__ Wbil) {
    long idx = (long)blockIdx.x * blockDim.x + threadIdx.x;
    if (idx >= (long)cD * cD / 4) return;
    long e0 = idx * 4;
    int r = (int)(e0 >> 11);
    int c = (int)(e0 & 2047);
    float4 v = *(const float4*)(Wbil + e0);
    float vv[4] = {v.x, v.y, v.z, v.w};
    bool bad = false;
#pragma unroll
    for (int q = 0; q < 4; q++) {
        float want = (r == c + q) ? 1.f : 0.f;
        if (vv[q] != want) bad = true;
    }
    if (bad) atomicOr(&g_flag, 1);
}

// ---------------- fp32 -> bf16 hi/lo split convert ----------------
__global__ void conv_split(const float* __restrict__ src,
                           __nv_bfloat16* __restrict__ H, __nv_bfloat16* __restrict__ L, long n4) {
    long idx = (long)blockIdx.x * blockDim.x + threadIdx.x;
    if (idx >= n4) return;
    float4 v = *(const float4*)(src + idx * 4);
    uint2 hv, lv;
    cvt_hl4(v, hv, lv);
    *(uint2*)(H + idx * 4) = hv;
    *(uint2*)(L + idx * 4) = lv;
}

// ---------------- W [Krows, H] -> Wt hi/lo [H, Krows] ----------------
__global__ void transpose_w(const float* __restrict__ W,
                            __nv_bfloat16* __restrict__ Th, __nv_bfloat16* __restrict__ Tl,
                            int outLd) {
    __shared__ float s[32][33];
    int n0 = blockIdx.x * 32;
    int k0 = blockIdx.y * 32;
    int tx = threadIdx.x & 31, ty = threadIdx.x >> 5;
#pragma unroll
    for (int i = 0; i < 4; i++)
        s[ty + 8 * i][tx] = W[(long)(k0 + ty + 8 * i) * cH + n0 + tx];
    __syncthreads();
#pragma unroll
    for (int i = 0; i < 4; i++) {
        float v = s[tx][ty + 8 * i];
        __nv_bfloat16 h = __float2bfloat16(v);
        __nv_bfloat16 l = __float2bfloat16(v - __bfloat162float(h));
        long o = (long)(n0 + ty + 8 * i) * outLd + k0 + tx;
        Th[o] = h; Tl[o] = l;
    }
}

// ---------------- ft @ W1_top partials ----------------
__global__ void ft_contrib(const float* __restrict__ ft, const float* __restrict__ W1,
                           float* __restrict__ Hbp) {
    __shared__ float sf[cB * 64];
    int jx = blockIdx.x * 128 + threadIdx.x;
    int s = blockIdx.y;
    int k0 = s * 64;
    for (int i = threadIdx.x; i < cB * 64; i += 128) {
        int b = i >> 6, k = i & 63;
        sf[i] = ft[(long)b * cD + k0 + k];
    }
    __syncthreads();
    float acc[cB];
#pragma unroll
    for (int b = 0; b < cB; b++) acc[b] = 0.f;
#pragma unroll
    for (int kk = 0; kk < 64; kk += 8) {
        float wv[8];
#pragma unroll
        for (int u = 0; u < 8; u++)
            wv[u] = W1[(long)(k0 + kk + u) * cH + jx];
#pragma unroll
        for (int u = 0; u < 8; u++)
#pragma unroll
            for (int b = 0; b < cB; b++) acc[b] += sf[b * 64 + kk + u] * wv[u];
    }
#pragma unroll
    for (int b = 0; b < cB; b++)
        Hbp[(long)s * cB * cH + (long)b * cH + jx] = acc[b];
}

__global__ void ft_sum(const float* __restrict__ Hbp, float* __restrict__ Hbs) {
    int idx = blockIdx.x * 256 + threadIdx.x;
    if (idx >= cB * cH) return;
    float s = 0.f;
#pragma unroll
    for (int p = 0; p < FT_SPLIT; p++) s += Hbp[(long)p * cB * cH + idx];
    Hbs[idx] = s;
}

__global__ void tproj_reduce(const float* __restrict__ P, float* __restrict__ tp) {
    if (g_flag == 0) return;
    long idx = (long)blockIdx.x * blockDim.x + threadIdx.x;
    const long n4 = (long)cB * cX * cD / 4;
    if (idx >= n4) return;
    float4 a = *(const float4*)(P + idx * 4);
    float4 b = *(const float4*)(P + n4 * 4 + idx * 4);
    *(float4*)(&tp[idx * 4]) = make_float4(a.x + b.x, a.y + b.y, a.z + b.z, a.w + b.w);
}

// ---------------- MLP tail ----------------
__global__ void mlp_reduce(const float* __restrict__ Hp, const float* __restrict__ b1,
                           const float* __restrict__ W2, const float* __restrict__ b2,
                           float* __restrict__ scores, int accumulate,
                           const float* __restrict__ Hb) {
    int row = blockIdx.x;
    int b = row >> 5;
    int tid = threadIdx.x;
    float s = 0.f;
    for (int j = tid; j < cH; j += 256) {
        float h = b1[j];
#pragma unroll
        for (int p = 0; p < MLP_SPLIT; p++) h += Hp[(long)p * ROWS * cH + (long)row * cH + j];
        if (Hb) h += Hb[(long)b * cH + j];
        h = fmaxf(h, 0.f);
        s += h * W2[j];
    }
    __shared__ float red[256];
    red[tid] = s;
    __syncthreads();
    for (int o = 128; o > 0; o >>= 1) {
        if (tid < o) red[tid] += red[tid + o];
        __syncthreads();
    }
    if (tid == 0) {
        float v = red[0] + b2[0];
        if (accumulate) scores[row] += v;
        else scores[row] = v;
    }
}

// ---------------- attention pooling per (b,i) -> X2 bf16 hi/lo ----------------
__global__ void attn_kernel(const float* __restrict__ inners,
                            const int* __restrict__ mt, const int* __restrict__ md,
                            const float* __restrict__ att_t, const float* __restrict__ att_d,
                            __nv_bfloat16* __restrict__ X2h, __nv_bfloat16* __restrict__ X2l) {
    int bi = blockIdx.x;
    int b = bi >> 5;
    int i = bi & 31;
    __shared__ float S[cX][cX];
    __shared__ float tw[cX], dw[cX];
    int tid = threadIdx.x;
    const long PS = (long)cB * cN * cX * 64;

    for (int idx = tid; idx < cX * cX; idx += 256) {
        int x = idx / cX, y = idx % cX;
        long o = ((long)b * (cN * cX) + i * cX + y) * 64 + x;
        float v = 0.f;
#pragma unroll
        for (int p = 0; p < INN_SPLIT; p++) v += inners[p * PS + o];
        int mm = mt[b * cX + x] * md[(b * cN + i) * cX + y];
        S[x][y] = (mm > 0) ? v : BIG_NEG_F;
    }
    __syncthreads();

    if (tid < cX) {
        float mx = -3.4e38f;
        for (int y = 0; y < cX; y++) mx = fmaxf(mx, S[tid][y]);
        tw[tid] = mx;
    } else if (tid < 2 * cX) {
        int y = tid - cX;
        float mx = -3.4e38f;
        for (int x = 0; x < cX; x++) mx = fmaxf(mx, S[x][y]);
        dw[y] = mx;
    }
    __syncthreads();

    if (tid == 0) {
        float m = -3.4e38f;
        for (int x = 0; x < cX; x++) m = fmaxf(m, tw[x]);
        float s = 0.f;
        for (int x = 0; x < cX; x++) { float e = expf(tw[x] - m); tw[x] = e; s += e; }
        float inv = 1.f / s;
        for (int x = 0; x < cX; x++) tw[x] *= inv;
    }
    if (tid == 32) {
        float m = -3.4e38f;
        for (int y = 0; y < cX; y++) m = fmaxf(m, dw[y]);
        float s = 0.f;
        for (int y = 0; y < cX; y++) { float e = expf(dw[y] - m); dw[y] = e; s += e; }
        float inv = 1.f / s;
        for (int y = 0; y < cX; y++) dw[y] *= inv;
    }
    __syncthreads();

    const float* tb = att_t + (long)b * cX * cD;
    const float* db = att_d + (long)(b * cN + i) * cX * cD;
    for (int d = tid; d < cD; d += 256) {
        float tf = 0.f, df = 0.f;
#pragma unroll
        for (int x = 0; x < cX; x++) {
            tf += tw[x] * tb[(long)x * cD + d];
            df += dw[x] * db[(long)x * cD + d];
        }
        __nv_bfloat16 th = __float2bfloat16(tf);
        __nv_bfloat16 tl = __float2bfloat16(tf - __bfloat162float(th));
        __nv_bfloat16 dh = __float2bfloat16(df);
        __nv_bfloat16 dl = __float2bfloat16(df - __bfloat162float(dh));
        long o = (long)bi * K2 + d;
        X2h[o] = th; X2l[o] = tl;
        X2h[o + cD] = dh; X2l[o + cD] = dl;
    }
}

// ---------------- final log_softmax ----------------
__global__ void logsoftmax_kernel(const float* __restrict__ scores, float* __restrict__ out) {
    int b = blockIdx.x;
    int n = threadIdx.x;
    float v = scores[b * cN + n];
    float m = v;
    for (int o = 16; o > 0; o >>= 1) m = fmaxf(m, __shfl_xor_sync(0xffffffffu, m, o));
    float e = expf(v - m);
    float s = e;
    for (int o = 16; o > 0; o >>= 1) s += __shfl_xor_sync(0xffffffffu, s, o);
    out[b * cN + n] = v - m - logf(s);
}

// ---------------- host ----------------
extern "C" void kernel_launch(void* const* d_in, const int* in_sizes, int n_in,
                              void* d_out, int out_size) {
    const float* fc_t = (const float*)d_in[0];
    const float* fc_d = (const float*)d_in[1];
    const float* att_t = (const float*)d_in[2];
    const float* att_d = (const float*)d_in[3];
    const int* am_t = (const int*)d_in[4];
    const int* am_d = (const int*)d_in[5];
    const float* W1 = (const float*)d_in[6];
    const float* b1 = (const float*)d_in[7];
    const float* W2 = (const float*)d_in[8];
    const float* b2 = (const float*)d_in[9];
    const float* Wbil = (const float*)d_in[10];
    const float* oW1 = (const float*)d_in[11];
    const float* ob1 = (const float*)d_in[12];
    const float* oW2 = (const float*)d_in[13];
    const float* ob2 = (const float*)d_in[14];
    float* out = (float*)d_out;

    float *Hp, *Hb, *Hbs, *tproj, *tprojP, *inn, *scores;
    __nv_bfloat16 *fdh, *fdl, *X2h, *X2l, *Wt1h, *Wt1l, *Wt2h, *Wt2l;
    cudaGetSymbolAddress((void**)&Hp, g_Hpart);
    cudaGetSymbolAddress((void**)&Hb, g_Hb);
    cudaGetSymbolAddress((void**)&Hbs, g_Hbs);
    cudaGetSymbolAddress((void**)&tproj, g_tproj);
    cudaGetSymbolAddress((void**)&tprojP, g_tprojP);
    cudaGetSymbolAddress((void**)&inn, g_inners);
    cudaGetSymbolAddress((void**)&scores, g_scores);
    cudaGetSymbolAddress((void**)&fdh, g_fdh);
    cudaGetSymbolAddress((void**)&fdl, g_fdl);
    cudaGetSymbolAddress((void**)&X2h, g_X2h);
    cudaGetSymbolAddress((void**)&X2l, g_X2l);
    cudaGetSymbolAddress((void**)&Wt1h, g_Wt1h);
    cudaGetSymbolAddress((void**)&Wt1l, g_Wt1l);
    cudaGetSymbolAddress((void**)&Wt2h, g_Wt2h);
    cudaGetSymbolAddress((void**)&Wt2l, g_Wt2l);

    static cudaStream_t s1 = nullptr;
    static cudaEvent_t evFork = nullptr, evJoin = nullptr;
    if (s1 == nullptr) {
        cudaStreamCreateWithFlags(&s1, cudaStreamNonBlocking);
        cudaEventCreateWithFlags(&evFork, cudaEventDisableTiming);
        cudaEventCreateWithFlags(&evJoin, cudaEventDisableTiming);
        cudaFuncSetAttribute((const void*)hgemm<0, 0>, cudaFuncAttributeMaxDynamicSharedMemorySize, SMEM_BYTES);
        cudaFuncSetAttribute((const void*)hgemm<0, 2>, cudaFuncAttributeMaxDynamicSharedMemorySize, SMEM_BYTES);
        cudaFuncSetAttribute((const void*)hgemm<1, 1>, cudaFuncAttributeMaxDynamicSharedMemorySize, SMEM_BYTES);
    }

    // ---- fork: stream1 runs the independent base-score chain ----
    cudaEventRecord(evFork, 0);
    cudaStreamWaitEvent(s1, evFork, 0);

    // [stream1] base-score chain + oW1 transpose
    conv_split<<<(ROWS * cD / 4 + 255) / 256, 256, 0, s1>>>(fc_d, fdh, fdl, (long)ROWS * cD / 4);
    transpose_w<<<dim3(cH / 32, cD / 32), 256, 0, s1>>>(W1 + (long)cD * cH, Wt1h, Wt1l, cD);
    transpose_w<<<dim3(cH / 32, K2 / 32), 256, 0, s1>>>(oW1, Wt2h, Wt2l, K2);
    ft_contrib<<<dim3(cH / 128, FT_SPLIT), 128, 0, s1>>>(fc_t, W1, Hb);
    ft_sum<<<(cB * cH + 255) / 256, 256, 0, s1>>>(Hb, Hbs);
    hgemm<1, 1><<<dim3(cH / 64, ROWS / 128, MLP_SPLIT), 256, SMEM_BYTES, s1>>>(
        nullptr, fdh, fdl, nullptr, nullptr, Wt1h, Wt1l, Hp,
        ROWS, cH, (cD / MLP_SPLIT) / 32, cD, cD, cH, MLP_SPLIT, 0,
        0, 0, 0, (long)(cD / MLP_SPLIT), (long)(cD / MLP_SPLIT), (long)ROWS * cH);
    mlp_reduce<<<ROWS, 256, 0, s1>>>(Hp, b1, W2, b2, scores, 0, Hbs);
    cudaEventRecord(evJoin, s1);

    // [default stream] inners chain
    init_flag_kernel<<<1, 1>>>();
    check_identity<<<(cD * cD / 4 + 255) / 256, 256>>>(Wbil);
    hgemm<0, 0><<<dim3(cD / 64, (cB * cX + 127) / 128, 2), 256, SMEM_BYTES>>>(
        att_t, nullptr, nullptr, Wbil, nullptr, nullptr, nullptr, tprojP,
        cB * cX, cD, (cD / 2) / 32, cD, cD, cD, 2, 1,
        0, 0, 0, (long)(cD / 2), (long)(cD / 2) * cD, (long)cB * cX * cD);
    tproj_reduce<<<(cB * cX * cD / 4 + 255) / 256, 256>>>(tprojP, tproj);
    // inners: per b, C[1152,64] = att_d_b[1152,*] @ B_b[36(clamp to 64),*]^T
    // B source selected on-device: att_t (identity) or tproj (general). K-split x4.
    hgemm<0, 2><<<dim3(1, (cN * cX) / 128, cB * INN_SPLIT), 256, SMEM_BYTES>>>(
        att_d, nullptr, nullptr, tproj, att_t, nullptr, nullptr, inn,
        cN * cX, 64, (cD / INN_SPLIT) / 32, cD, cD, cX, INN_SPLIT, 0,
        (long)cN * cX * cD, (long)cX * cD, (long)cN * cX * 64,
        (long)(cD / INN_SPLIT), (long)(cD / INN_SPLIT), (long)cB * cN * cX * 64);
    attn_kernel<<<ROWS, 256>>>(inn, am_t, am_d, att_t, att_d, X2h, X2l);

    // ---- join: object MLP needs X2 (default) + Wt2/scores (stream1) ----
    cudaStreamWaitEvent(0, evJoin, 0);

    hgemm<1, 1><<<dim3(cH / 64, ROWS / 128, MLP_SPLIT), 256, SMEM_BYTES>>>(
        nullptr, X2h, X2l, nullptr, nullptr, Wt2h, Wt2l, Hp,
        ROWS, cH, (K2 / MLP_SPLIT) / 32, K2, K2, cH, MLP_SPLIT, 0,
        0, 0, 0, (long)(K2 / MLP_SPLIT), (long)(K2 / MLP_SPLIT), (long)ROWS * cH);
    mlp_reduce<<<ROWS, 256>>>(Hp, ob1, oW2, ob2, scores, 1, nullptr);

    logsoftmax_kernel<<<cB, 32>>>(scores, out);
}

// round 13
// speedup vs baseline: 1.0469x; 1.0469x over previous
#include <cuda_runtime.h>
#include <cuda_bf16.h>
#include <math.h>
#include <stdint.h>

// Problem constants
constexpr int cB = 16;
constexpr int cN = 32;
constexpr int cX = 36;
constexpr int cD = 2048;
constexpr int cH = 512;
constexpr int ROWS = cB * cN;     // 512
constexpr int K2 = 2 * cD;        // 4096
constexpr int MLP_SPLIT = 8;
constexpr int INN_SPLIT = 2;
constexpr int FT_SPLIT = 32;
#define BIG_NEG_F (-1000000000.0f)

// ---------------- scratch ----------------
__device__ __nv_bfloat16 g_fdh[ROWS * cD], g_fdl[ROWS * cD];
__device__ __nv_bfloat16 g_X2h[ROWS * K2], g_X2l[ROWS * K2];
__device__ __nv_bfloat16 g_Wt1h[cH * cD], g_Wt1l[cH * cD];
__device__ __nv_bfloat16 g_Wt2h[cH * K2], g_Wt2l[cH * K2];
__device__ float g_Hb[FT_SPLIT * cB * cH];
__device__ float g_Hbs[cB * cH];
__device__ float g_Hpart[MLP_SPLIT * ROWS * cH];
__device__ float g_tproj[cB * cX * cD];
__device__ float g_tprojP[2 * cB * cX * cD];
__device__ float g_inners[INN_SPLIT * cB * cN * cX * 64];
__device__ float g_scores[ROWS];
__device__ int g_flag;   // 0 = Wbil identity, 1 = general

// ---------------- helpers ----------------
__device__ __forceinline__ uint32_t smem_u32(const void* p) {
    uint32_t a;
    asm("{ .reg .u64 t; cvta.to.shared.u64 t, %1; cvt.u32.u64 %0, t; }" : "=r"(a) : "l"(p));
    return a;
}
__device__ __forceinline__ void ldsm4(uint32_t* r, uint32_t addr) {
    asm volatile("ldmatrix.sync.aligned.m8n8.x4.shared.b16 {%0,%1,%2,%3}, [%4];"
                 : "=r"(r[0]), "=r"(r[1]), "=r"(r[2]), "=r"(r[3]) : "r"(addr));
}
__device__ __forceinline__ void mma_bf16(float* c, const uint32_t* a, uint32_t b0, uint32_t b1) {
    asm volatile("mma.sync.aligned.m16n8k16.row.col.f32.bf16.bf16.f32 "
                 "{%0,%1,%2,%3}, {%4,%5,%6,%7}, {%8,%9}, {%0,%1,%2,%3};"
                 : "+f"(c[0]), "+f"(c[1]), "+f"(c[2]), "+f"(c[3])
                 : "r"(a[0]), "r"(a[1]), "r"(a[2]), "r"(a[3]), "r"(b0), "r"(b1));
}
__device__ __forceinline__ void cvt_hl4(float4 v, uint2& hv, uint2& lv) {
    __nv_bfloat16 hx = __float2bfloat16(v.x), hy = __float2bfloat16(v.y);
    __nv_bfloat16 hz = __float2bfloat16(v.z), hw = __float2bfloat16(v.w);
    __nv_bfloat16 lx = __float2bfloat16(v.x - __bfloat162float(hx));
    __nv_bfloat16 ly = __float2bfloat16(v.y - __bfloat162float(hy));
    __nv_bfloat16 lz = __float2bfloat16(v.z - __bfloat162float(hz));
    __nv_bfloat16 lw = __float2bfloat16(v.w - __bfloat162float(hw));
    hv.x = ((uint32_t)__bfloat16_as_ushort(hy) << 16) | __bfloat16_as_ushort(hx);
    hv.y = ((uint32_t)__bfloat16_as_ushort(hw) << 16) | __bfloat16_as_ushort(hz);
    lv.x = ((uint32_t)__bfloat16_as_ushort(ly) << 16) | __bfloat16_as_ushort(lx);
    lv.y = ((uint32_t)__bfloat16_as_ushort(lw) << 16) | __bfloat16_as_ushort(lz);
}

// SMEM element-offset layout per buffer (bf16 units). Row stride 24 elements.
constexpr int sAH = 0;              // [2][128][24]
constexpr int sAL = 6144;
constexpr int sBH = 12288;          // [2][64][24]
constexpr int sBL = 15360;
constexpr int SM_ELEMS = 18432;
constexpr int SMEM_BYTES = 2 * SM_ELEMS * 2;   // 73,728 B

// ======== compute phase: one 32-K chunk from a buffer ========
__device__ __forceinline__ void compute_chunk(uint32_t cb, int mrow, int nrow, int g, int r8,
                                              float acc[2][4][4]) {
#pragma unroll
    for (int ks = 0; ks < 2; ks++) {
        uint32_t ah[2][4], al[2][4], bh[2][4], bl[2][4];
#pragma unroll
        for (int mt = 0; mt < 2; mt++) {
            int row = mrow + mt * 16 + (g & 1) * 8 + r8;
            uint32_t bo = (uint32_t)(((ks * 128 + row) * 24 + (g >> 1) * 8) * 2);
            ldsm4(ah[mt], cb + sAH * 2 + bo);
            ldsm4(al[mt], cb + sAL * 2 + bo);
        }
#pragma unroll
        for (int bt = 0; bt < 2; bt++) {
            int row = nrow + bt * 16 + (g >> 1) * 8 + r8;
            uint32_t bo = (uint32_t)(((ks * 64 + row) * 24 + (g & 1) * 8) * 2);
            ldsm4(bh[bt], cb + sBH * 2 + bo);
            ldsm4(bl[bt], cb + sBL * 2 + bo);
        }
#pragma unroll
        for (int mi = 0; mi < 2; mi++)
#pragma unroll
            for (int nj = 0; nj < 4; nj++) {
                int bt = nj >> 1, sub = (nj & 1) * 2;
                mma_bf16(acc[mi][nj], ah[mi], bh[bt][sub], bh[bt][sub + 1]);
                mma_bf16(acc[mi][nj], ah[mi], bl[bt][sub], bl[bt][sub + 1]);
                mma_bf16(acc[mi][nj], al[mi], bh[bt][sub], bh[bt][sub + 1]);
            }
    }
}

// ============ bf16-split HMMA GEMM: AM/BM modes, 2-stage register pipeline ============
// AM: 0 = gA fp32 [M,K], convert in-loop. 1 = gAh/gAl bf16 [M,K] pre-split.
// BM: 0 = gB fp32 [K,N] (NN transpose in STS). 1 = gBh/gBl bf16 [N,K] pre-split.
//     2 = fp32 [N,K] (NT) with row clamp to Bn; source = gB2 if g_flag==0 else gB.
template <int AM, int BM>
__global__ __launch_bounds__(256, 2)
void hgemm(const float* __restrict__ gA,
           const __nv_bfloat16* __restrict__ gAh, const __nv_bfloat16* __restrict__ gAl,
           const float* __restrict__ gB, const float* __restrict__ gB2,
           const __nv_bfloat16* __restrict__ gBh, const __nv_bfloat16* __restrict__ gBl,
           float* __restrict__ gC,
           int M, int Nld, int Kchunks, int lda, int ldb, int Bn, int nsplit, int onlyFallback,
           long sAb, long sBb, long sCb, long sAk, long sBk, long sCk) {
    if (onlyFallback && g_flag == 0) return;
    extern __shared__ __align__(16) uint16_t sm[];
    const int zb = blockIdx.z / nsplit;
    const int zs = blockIdx.z - zb * nsplit;
    if (AM == 0) gA += (long)zb * sAb + (long)zs * sAk;
    else { gAh += (long)zb * sAb + (long)zs * sAk; gAl += (long)zb * sAb + (long)zs * sAk; }
    if (BM == 1) { gBh += (long)zb * sBb + (long)zs * sBk; gBl += (long)zb * sBb + (long)zs * sBk; }
    else if (BM == 0) gB += (long)zb * sBb + (long)zs * sBk;
    else {
        const float* src = (g_flag == 0) ? gB2 : gB;
        gB = src + (long)zb * sBb + (long)zs * sBk;
    }
    gC += (long)zb * sCb + (long)zs * sCk;
    const int m0 = blockIdx.y * 128;
    const int n0 = blockIdx.x * 64;
    const int tid = threadIdx.x;
    const int lane = tid & 31;
    const int w = tid >> 5;
    const int mrow = (w & 3) * 32;
    const int nrow = (w >> 2) * 32;
    const uint32_t sbase = smem_u32(sm);

    float4 ra[4];
    uint4 pah[2], pal[2];
    float4 rbf[2];
    uint4 pbh, pbl;

    int a_r[4], a_j[4];
    if (AM == 0) {
#pragma unroll
        for (int it = 0; it < 4; it++) { int f = it * 256 + tid; a_r[it] = f >> 3; a_j[it] = f & 7; }
    } else {
#pragma unroll
        for (int it = 0; it < 2; it++) { int f = it * 256 + tid; a_r[it] = f >> 2; a_j[it] = f & 3; }
    }
    int b_r[2], b_j[2];
    if (BM == 0) {
#pragma unroll
        for (int it = 0; it < 2; it++) { int f = it * 256 + tid; b_r[it] = f >> 4; b_j[it] = f & 15; }
    } else if (BM == 2) {
#pragma unroll
        for (int it = 0; it < 2; it++) { int f = it * 256 + tid; b_r[it] = f >> 3; b_j[it] = f & 7; }
    } else {
        b_r[0] = tid >> 2; b_j[0] = tid & 3;
    }

    auto loadA = [&](int k0) {
        if (AM == 0) {
#pragma unroll
            for (int it = 0; it < 4; it++) {
                ra[it] = make_float4(0.f, 0.f, 0.f, 0.f);
                if (m0 + a_r[it] < M)
                    ra[it] = *(const float4*)(gA + (long)(m0 + a_r[it]) * lda + k0 + a_j[it] * 4);
            }
        } else {
#pragma unroll
            for (int it = 0; it < 2; it++) {
                pah[it] = make_uint4(0, 0, 0, 0); pal[it] = make_uint4(0, 0, 0, 0);
                if (m0 + a_r[it] < M) {
                    long base = (long)(m0 + a_r[it]) * lda + k0 + a_j[it] * 8;
                    pah[it] = *(const uint4*)(gAh + base);
                    pal[it] = *(const uint4*)(gAl + base);
                }
            }
        }
    };
    auto loadB = [&](int k0) {
        if (BM == 0) {
#pragma unroll
            for (int it = 0; it < 2; it++)
                rbf[it] = *(const float4*)(gB + (long)(k0 + b_r[it]) * ldb + n0 + b_j[it] * 4);
        } else if (BM == 2) {
#pragma unroll
            for (int it = 0; it < 2; it++) {
                int rr = min(n0 + b_r[it], Bn - 1);
                rbf[it] = *(const float4*)(gB + (long)rr * ldb + k0 + b_j[it] * 4);
            }
        } else {
            long base = (long)(n0 + b_r[0]) * ldb + k0 + b_j[0] * 8;
            pbh = *(const uint4*)(gBh + base);
            pbl = *(const uint4*)(gBl + base);
        }
    };
    auto storeA = [&](uint16_t* bp) {
        if (AM == 0) {
#pragma unroll
            for (int it = 0; it < 4; it++) {
                uint2 hv, lv;
                cvt_hl4(ra[it], hv, lv);
                int off = (((a_j[it] >> 2) * 128 + a_r[it]) * 24) + (a_j[it] & 3) * 4;
                *(uint2*)&bp[sAH + off] = hv;
                *(uint2*)&bp[sAL + off] = lv;
            }
        } else {
#pragma unroll
            for (int it = 0; it < 2; it++) {
                int off = (((a_j[it] >> 1) * 128 + a_r[it]) * 24) + (a_j[it] & 1) * 8;
                *(uint4*)&bp[sAH + off] = pah[it];
                *(uint4*)&bp[sAL + off] = pal[it];
            }
        }
    };
    auto storeB = [&](uint16_t* bp) {
        if (BM == 0) {
#pragma unroll
            for (int it = 0; it < 2; it++) {
                float vv[4] = {rbf[it].x, rbf[it].y, rbf[it].z, rbf[it].w};
                int h = b_r[it] >> 4, kk = b_r[it] & 15;
#pragma unroll
                for (int e = 0; e < 4; e++) {
                    int n = b_j[it] * 4 + e;
                    __nv_bfloat16 hb = __float2bfloat16(vv[e]);
                    __nv_bfloat16 lb = __float2bfloat16(vv[e] - __bfloat162float(hb));
                    int off = ((h * 64 + n) * 24) + kk;
                    bp[sBH + off] = __bfloat16_as_ushort(hb);
                    bp[sBL + off] = __bfloat16_as_ushort(lb);
                }
            }
        } else if (BM == 2) {
#pragma unroll
            for (int it = 0; it < 2; it++) {
                uint2 hv, lv;
                cvt_hl4(rbf[it], hv, lv);
                int off = (((b_j[it] >> 2) * 64 + b_r[it]) * 24) + (b_j[it] & 3) * 4;
                *(uint2*)&bp[sBH + off] = hv;
                *(uint2*)&bp[sBL + off] = lv;
            }
        } else {
            int off = (((b_j[0] >> 1) * 64 + b_r[0]) * 24) + (b_j[0] & 1) * 8;
            *(uint4*)&bp[sBH + off] = pbh;
            *(uint4*)&bp[sBL + off] = pbl;
        }
    };

    float acc[2][4][4];
#pragma unroll
    for (int i = 0; i < 2; i++)
#pragma unroll
        for (int j = 0; j < 4; j++)
#pragma unroll
            for (int q = 0; q < 4; q++) acc[i][j][q] = 0.f;

    const int g = lane >> 3, r8 = lane & 7;

    loadA(0); loadB(0);
    storeA(sm); storeB(sm);
    __syncthreads();
    if (Kchunks > 1) { loadA(32); loadB(32); }

    for (int c = 0; c < Kchunks; c++) {
        if (c + 1 < Kchunks) {
            uint16_t* bp = sm + ((c + 1) & 1) * SM_ELEMS;
            storeA(bp); storeB(bp);
        }
        if (c + 2 < Kchunks) { loadA((c + 2) * 32); loadB((c + 2) * 32); }
        compute_chunk(sbase + (uint32_t)((c & 1) * SM_ELEMS * 2), mrow, nrow, g, r8, acc);
        __syncthreads();
    }

#pragma unroll
    for (int mi = 0; mi < 2; mi++) {
        int rg = m0 + mrow + mi * 16 + (lane >> 2);
#pragma unroll
        for (int nj = 0; nj < 4; nj++) {
            int cg = n0 + nrow + nj * 8 + 2 * (lane & 3);
            if (rg < M) {
                *(float2*)(gC + (long)rg * Nld + cg) = make_float2(acc[mi][nj][0], acc[mi][nj][1]);
            }
            if (rg + 8 < M) {
                *(float2*)(gC + (long)(rg + 8) * Nld + cg) = make_float2(acc[mi][nj][2], acc[mi][nj][3]);
            }
        }
    }
}

// ---------------- flag init + identity check ----------------
__global__ void init_flag_kernel() { g_flag = 0; }

__global__ void check_identity(const float* __restrict__ Wbil) {
    long idx = (long)blockIdx.x * blockDim.x + threadIdx.x;
    if (idx >= (long)cD * cD / 4) return;
    long e0 = idx * 4;
    int r = (int)(e0 >> 11);
    int c = (int)(e0 & 2047);
    float4 v = *(const float4*)(Wbil + e0);
    float vv[4] = {v.x, v.y, v.z, v.w};
    bool bad = false;
#pragma unroll
    for (int q = 0; q < 4; q++) {
        float want = (r == c + q) ? 1.f : 0.f;
        if (vv[q] != want) bad = true;
    }
    if (bad) atomicOr(&g_flag, 1);
}

// ---------------- fp32 -> bf16 hi/lo split convert ----------------
__global__ void conv_split(const float* __restrict__ src,
                           __nv_bfloat16* __restrict__ H, __nv_bfloat16* __restrict__ L, long n4) {
    long idx = (long)blockIdx.x * blockDim.x + threadIdx.x;
    if (idx >= n4) return;
    float4 v = *(const float4*)(src + idx * 4);
    uint2 hv, lv;
    cvt_hl4(v, hv, lv);
    *(uint2*)(H + idx * 4) = hv;
    *(uint2*)(L + idx * 4) = lv;
}

// ---------------- W [Krows, H] -> Wt hi/lo [H, Krows] ----------------
__global__ void transpose_w(const float* __restrict__ W,
                            __nv_bfloat16* __restrict__ Th, __nv_bfloat16* __restrict__ Tl,
                            int outLd) {
    __shared__ float s[32][33];
    int n0 = blockIdx.x * 32;
    int k0 = blockIdx.y * 32;
    int tx = threadIdx.x & 31, ty = threadIdx.x >> 5;
#pragma unroll
    for (int i = 0; i < 4; i++)
        s[ty + 8 * i][tx] = W[(long)(k0 + ty + 8 * i) * cH + n0 + tx];
    __syncthreads();
#pragma unroll
    for (int i = 0; i < 4; i++) {
        float v = s[tx][ty + 8 * i];
        __nv_bfloat16 h = __float2bfloat16(v);
        __nv_bfloat16 l = __float2bfloat16(v - __bfloat162float(h));
        long o = (long)(n0 + ty + 8 * i) * outLd + k0 + tx;
        Th[o] = h; Tl[o] = l;
    }
}

// ---------------- ft @ W1_top partials ----------------
__global__ void ft_contrib(const float* __restrict__ ft, const float* __restrict__ W1,
                           float* __restrict__ Hbp) {
    __shared__ float sf[cB * 64];
    int jx = blockIdx.x * 128 + threadIdx.x;
    int s = blockIdx.y;
    int k0 = s * 64;
    for (int i = threadIdx.x; i < cB * 64; i += 128) {
        int b = i >> 6, k = i & 63;
        sf[i] = ft[(long)b * cD + k0 + k];
    }
    __syncthreads();
    float acc[cB];
#pragma unroll
    for (int b = 0; b < cB; b++) acc[b] = 0.f;
#pragma unroll
    for (int kk = 0; kk < 64; kk += 8) {
        float wv[8];
#pragma unroll
        for (int u = 0; u < 8; u++)
            wv[u] = W1[(long)(k0 + kk + u) * cH + jx];
#pragma unroll
        for (int u = 0; u < 8; u++)
#pragma unroll
            for (int b = 0; b < cB; b++) acc[b] += sf[b * 64 + kk + u] * wv[u];
    }
#pragma unroll
    for (int b = 0; b < cB; b++)
        Hbp[(long)s * cB * cH + (long)b * cH + jx] = acc[b];
}

__global__ void ft_sum(const float* __restrict__ Hbp, float* __restrict__ Hbs) {
    int idx = blockIdx.x * 256 + threadIdx.x;
    if (idx >= cB * cH) return;
    float s = 0.f;
#pragma unroll
    for (int p = 0; p < FT_SPLIT; p++) s += Hbp[(long)p * cB * cH + idx];
    Hbs[idx] = s;
}

__global__ void tproj_reduce(const float* __restrict__ P, float* __restrict__ tp) {
    if (g_flag == 0) return;
    long idx = (long)blockIdx.x * blockDim.x + threadIdx.x;
    const long n4 = (long)cB * cX * cD / 4;
    if (idx >= n4) return;
    float4 a = *(const float4*)(P + idx * 4);
    float4 b = *(const float4*)(P + n4 * 4 + idx * 4);
    *(float4*)(&tp[idx * 4]) = make_float4(a.x + b.x, a.y + b.y, a.z + b.z, a.w + b.w);
}

// ---------------- MLP tail ----------------
__global__ void mlp_reduce(const float* __restrict__ Hp, const float* __restrict__ b1,
                           const float* __restrict__ W2, const float* __restrict__ b2,
                           float* __restrict__ scores, int accumulate,
                           const float* __restrict__ Hb) {
    int row = blockIdx.x;
    int b = row >> 5;
    int tid = threadIdx.x;
    float s = 0.f;
    for (int j = tid; j < cH; j += 256) {
        float h = b1[j];
#pragma unroll
        for (int p = 0; p < MLP_SPLIT; p++) h += Hp[(long)p * ROWS * cH + (long)row * cH + j];
        if (Hb) h += Hb[(long)b * cH + j];
        h = fmaxf(h, 0.f);
        s += h * W2[j];
    }
    __shared__ float red[256];
    red[tid] = s;
    __syncthreads();
    for (int o = 128; o > 0; o >>= 1) {
        if (tid < o) red[tid] += red[tid + o];
        __syncthreads();
    }
    if (tid == 0) {
        float v = red[0] + b2[0];
        if (accumulate) scores[row] += v;
        else scores[row] = v;
    }
}

// ---------------- attention pooling per (b,i) -> X2 bf16 hi/lo ----------------
__global__ void attn_kernel(const float* __restrict__ inners,
                            const int* __restrict__ mt, const int* __restrict__ md,
                            const float* __restrict__ att_t, const float* __restrict__ att_d,
                            __nv_bfloat16* __restrict__ X2h, __nv_bfloat16* __restrict__ X2l) {
    int bi = blockIdx.x;
    int b = bi >> 5;
    int i = bi & 31;
    __shared__ float S[cX][cX];
    __shared__ float tw[cX], dw[cX];
    int tid = threadIdx.x;
    const long PS = (long)cB * cN * cX * 64;

    for (int idx = tid; idx < cX * cX; idx += 256) {
        int x = idx / cX, y = idx % cX;
        long o = ((long)b * (cN * cX) + i * cX + y) * 64 + x;
        float v = 0.f;
#pragma unroll
        for (int p = 0; p < INN_SPLIT; p++) v += inners[p * PS + o];
        int mm = mt[b * cX + x] * md[(b * cN + i) * cX + y];
        S[x][y] = (mm > 0) ? v : BIG_NEG_F;
    }
    __syncthreads();

    if (tid < cX) {
        float mx = -3.4e38f;
        for (int y = 0; y < cX; y++) mx = fmaxf(mx, S[tid][y]);
        tw[tid] = mx;
    } else if (tid < 2 * cX) {
        int y = tid - cX;
        float mx = -3.4e38f;
        for (int x = 0; x < cX; x++) mx = fmaxf(mx, S[x][y]);
        dw[y] = mx;
    }
    __syncthreads();

    if (tid == 0) {
        float m = -3.4e38f;
        for (int x = 0; x < cX; x++) m = fmaxf(m, tw[x]);
        float s = 0.f;
        for (int x = 0; x < cX; x++) { float e = expf(tw[x] - m); tw[x] = e; s += e; }
        float inv = 1.f / s;
        for (int x = 0; x < cX; x++) tw[x] *= inv;
    }
    if (tid == 32) {
        float m = -3.4e38f;
        for (int y = 0; y < cX; y++) m = fmaxf(m, dw[y]);
        float s = 0.f;
        for (int y = 0; y < cX; y++) { float e = expf(dw[y] - m); dw[y] = e; s += e; }
        float inv = 1.f / s;
        for (int y = 0; y < cX; y++) dw[y] *= inv;
    }
    __syncthreads();

    const float* tb = att_t + (long)b * cX * cD;
    const float* db = att_d + (long)(b * cN + i) * cX * cD;
    for (int d = tid; d < cD; d += 256) {
        float tf = 0.f, df = 0.f;
#pragma unroll
        for (int x = 0; x < cX; x++) {
            tf += tw[x] * tb[(long)x * cD + d];
            df += dw[x] * db[(long)x * cD + d];
        }
        __nv_bfloat16 th = __float2bfloat16(tf);
        __nv_bfloat16 tl = __float2bfloat16(tf - __bfloat162float(th));
        __nv_bfloat16 dh = __float2bfloat16(df);
        __nv_bfloat16 dl = __float2bfloat16(df - __bfloat162float(dh));
        long o = (long)bi * K2 + d;
        X2h[o] = th; X2l[o] = tl;
        X2h[o + cD] = dh; X2l[o + cD] = dl;
    }
}

// ---------------- final log_softmax ----------------
__global__ void logsoftmax_kernel(const float* __restrict__ scores, float* __restrict__ out) {
    int b = blockIdx.x;
    int n = threadIdx.x;
    float v = scores[b * cN + n];
    float m = v;
    for (int o = 16; o > 0; o >>= 1) m = fmaxf(m, __shfl_xor_sync(0xffffffffu, m, o));
    float e = expf(v - m);
    float s = e;
    for (int o = 16; o > 0; o >>= 1) s += __shfl_xor_sync(0xffffffffu, s, o);
    out[b * cN + n] = v - m - logf(s);
}

// ---------------- host ----------------
extern "C" void kernel_launch(void* const* d_in, const int* in_sizes, int n_in,
                              void* d_out, int out_size) {
    const float* fc_t = (const float*)d_in[0];
    const float* fc_d = (const float*)d_in[1];
    const float* att_t = (const float*)d_in[2];
    const float* att_d = (const float*)d_in[3];
    const int* am_t = (const int*)d_in[4];
    const int* am_d = (const int*)d_in[5];
    const float* W1 = (const float*)d_in[6];
    const float* b1 = (const float*)d_in[7];
    const float* W2 = (const float*)d_in[8];
    const float* b2 = (const float*)d_in[9];
    const float* Wbil = (const float*)d_in[10];
    const float* oW1 = (const float*)d_in[11];
    const float* ob1 = (const float*)d_in[12];
    const float* oW2 = (const float*)d_in[13];
    const float* ob2 = (const float*)d_in[14];
    float* out = (float*)d_out;

    float *Hp, *Hb, *Hbs, *tproj, *tprojP, *inn, *scores;
    __nv_bfloat16 *fdh, *fdl, *X2h, *X2l, *Wt1h, *Wt1l, *Wt2h, *Wt2l;
    cudaGetSymbolAddress((void**)&Hp, g_Hpart);
    cudaGetSymbolAddress((void**)&Hb, g_Hb);
    cudaGetSymbolAddress((void**)&Hbs, g_Hbs);
    cudaGetSymbolAddress((void**)&tproj, g_tproj);
    cudaGetSymbolAddress((void**)&tprojP, g_tprojP);
    cudaGetSymbolAddress((void**)&inn, g_inners);
    cudaGetSymbolAddress((void**)&scores, g_scores);
    cudaGetSymbolAddress((void**)&fdh, g_fdh);
    cudaGetSymbolAddress((void**)&fdl, g_fdl);
    cudaGetSymbolAddress((void**)&X2h, g_X2h);
    cudaGetSymbolAddress((void**)&X2l, g_X2l);
    cudaGetSymbolAddress((void**)&Wt1h, g_Wt1h);
    cudaGetSymbolAddress((void**)&Wt1l, g_Wt1l);
    cudaGetSymbolAddress((void**)&Wt2h, g_Wt2h);
    cudaGetSymbolAddress((void**)&Wt2l, g_Wt2l);

    static cudaStream_t s1 = nullptr;
    static cudaEvent_t evFork = nullptr, evJoin = nullptr;
    if (s1 == nullptr) {
        cudaStreamCreateWithFlags(&s1, cudaStreamNonBlocking);
        cudaEventCreateWithFlags(&evFork, cudaEventDisableTiming);
        cudaEventCreateWithFlags(&evJoin, cudaEventDisableTiming);
        cudaFuncSetAttribute((const void*)hgemm<0, 0>, cudaFuncAttributeMaxDynamicSharedMemorySize, SMEM_BYTES);
        cudaFuncSetAttribute((const void*)hgemm<0, 2>, cudaFuncAttributeMaxDynamicSharedMemorySize, SMEM_BYTES);
        cudaFuncSetAttribute((const void*)hgemm<1, 1>, cudaFuncAttributeMaxDynamicSharedMemorySize, SMEM_BYTES);
    }

    // ---- fork: stream1 runs the independent base-score chain ----
    cudaEventRecord(evFork, 0);
    cudaStreamWaitEvent(s1, evFork, 0);

    // [stream1] base-score chain + oW1 transpose
    conv_split<<<(ROWS * cD / 4 + 255) / 256, 256, 0, s1>>>(fc_d, fdh, fdl, (long)ROWS * cD / 4);
    transpose_w<<<dim3(cH / 32, cD / 32), 256, 0, s1>>>(W1 + (long)cD * cH, Wt1h, Wt1l, cD);
    transpose_w<<<dim3(cH / 32, K2 / 32), 256, 0, s1>>>(oW1, Wt2h, Wt2l, K2);
    ft_contrib<<<dim3(cH / 128, FT_SPLIT), 128, 0, s1>>>(fc_t, W1, Hb);
    ft_sum<<<(cB * cH + 255) / 256, 256, 0, s1>>>(Hb, Hbs);
    hgemm<1, 1><<<dim3(cH / 64, ROWS / 128, MLP_SPLIT), 256, SMEM_BYTES, s1>>>(
        nullptr, fdh, fdl, nullptr, nullptr, Wt1h, Wt1l, Hp,
        ROWS, cH, (cD / MLP_SPLIT) / 32, cD, cD, cH, MLP_SPLIT, 0,
        0, 0, 0, (long)(cD / MLP_SPLIT), (long)(cD / MLP_SPLIT), (long)ROWS * cH);
    mlp_reduce<<<ROWS, 256, 0, s1>>>(Hp, b1, W2, b2, scores, 0, Hbs);
    cudaEventRecord(evJoin, s1);

    // [default stream] inners chain
    init_flag_kernel<<<1, 1>>>();
    check_identity<<<(cD * cD / 4 + 255) / 256, 256>>>(Wbil);
    hgemm<0, 0><<<dim3(cD / 64, (cB * cX + 127) / 128, 2), 256, SMEM_BYTES>>>(
        att_t, nullptr, nullptr, Wbil, nullptr, nullptr, nullptr, tprojP,
        cB * cX, cD, (cD / 2) / 32, cD, cD, cD, 2, 1,
        0, 0, 0, (long)(cD / 2), (long)(cD / 2) * cD, (long)cB * cX * cD);
    tproj_reduce<<<(cB * cX * cD / 4 + 255) / 256, 256>>>(tprojP, tproj);
    // inners: per b, C[1152,64] = att_d_b[1152,*] @ B_b[36(clamp to 64),*]^T
    // B source selected on-device: att_t (identity) or tproj (general). K-split x2.
    hgemm<0, 2><<<dim3(1, (cN * cX) / 128, cB * INN_SPLIT), 256, SMEM_BYTES>>>(
        att_d, nullptr, nullptr, tproj, att_t, nullptr, nullptr, inn,
        cN * cX, 64, (cD / INN_SPLIT) / 32, cD, cD, cX, INN_SPLIT, 0,
        (long)cN * cX * cD, (long)cX * cD, (long)cN * cX * 64,
        (long)(cD / INN_SPLIT), (long)(cD / INN_SPLIT), (long)cB * cN * cX * 64);
    attn_kernel<<<ROWS, 256>>>(inn, am_t, am_d, att_t, att_d, X2h, X2l);

    // ---- join: object MLP needs X2 (default) + Wt2/scores (stream1) ----
    cudaStreamWaitEvent(0, evJoin, 0);

    hgemm<1, 1><<<dim3(cH / 64, ROWS / 128, MLP_SPLIT), 256, SMEM_BYTES>>>(
        nullptr, X2h, X2l, nullptr, nullptr, Wt2h, Wt2l, Hp,
        ROWS, cH, (K2 / MLP_SPLIT) / 32, K2, K2, cH, MLP_SPLIT, 0,
        0, 0, 0, (long)(K2 / MLP_SPLIT), (long)(K2 / MLP_SPLIT), (long)ROWS * cH);
    mlp_reduce<<<ROWS, 256>>>(Hp, ob1, oW2, ob2, scores, 1, nullptr);

    logsoftmax_kernel<<<cB, 32>>>(scores, out);
}

// round 14
// speedup vs baseline: 1.0903x; 1.0415x over previous
#include <cuda_runtime.h>
#include <cuda_bf16.h>
#include <math.h>
#include <stdint.h>

// Problem constants
constexpr int cB = 16;
constexpr int cN = 32;
constexpr int cX = 36;
constexpr int cD = 2048;
constexpr int cH = 512;
constexpr int ROWS = cB * cN;     // 512
constexpr int K2 = 2 * cD;        // 4096
constexpr int MLP_SPLIT = 8;
constexpr int INN_SPLIT = 2;
constexpr int FT_SPLIT = 32;
constexpr int NGRP = 2;           // batch groups for pipelining
constexpr int GB = cB / NGRP;     // 8 batches per group
#define BIG_NEG_F (-1000000000.0f)

// ---------------- scratch ----------------
__device__ __nv_bfloat16 g_fdh[ROWS * cD], g_fdl[ROWS * cD];
__device__ __nv_bfloat16 g_X2h[ROWS * K2], g_X2l[ROWS * K2];
__device__ __nv_bfloat16 g_Wt1h[cH * cD], g_Wt1l[cH * cD];
__device__ __nv_bfloat16 g_Wt2h[cH * K2], g_Wt2l[cH * K2];
__device__ float g_Hb[FT_SPLIT * cB * cH];
__device__ float g_Hbs[cB * cH];
__device__ float g_Hpart[MLP_SPLIT * ROWS * cH];
__device__ float g_tproj[cB * cX * cD];
__device__ float g_tprojP[2 * cB * cX * cD];
__device__ float g_inners[INN_SPLIT * cB * cN * cX * 64];
__device__ float g_scores[ROWS];
__device__ int g_flag;   // 0 = Wbil identity, 1 = general

// ---------------- helpers ----------------
__device__ __forceinline__ uint32_t smem_u32(const void* p) {
    uint32_t a;
    asm("{ .reg .u64 t; cvta.to.shared.u64 t, %1; cvt.u32.u64 %0, t; }" : "=r"(a) : "l"(p));
    return a;
}
__device__ __forceinline__ void ldsm4(uint32_t* r, uint32_t addr) {
    asm volatile("ldmatrix.sync.aligned.m8n8.x4.shared.b16 {%0,%1,%2,%3}, [%4];"
                 : "=r"(r[0]), "=r"(r[1]), "=r"(r[2]), "=r"(r[3]) : "r"(addr));
}
__device__ __forceinline__ void mma_bf16(float* c, const uint32_t* a, uint32_t b0, uint32_t b1) {
    asm volatile("mma.sync.aligned.m16n8k16.row.col.f32.bf16.bf16.f32 "
                 "{%0,%1,%2,%3}, {%4,%5,%6,%7}, {%8,%9}, {%0,%1,%2,%3};"
                 : "+f"(c[0]), "+f"(c[1]), "+f"(c[2]), "+f"(c[3])
                 : "r"(a[0]), "r"(a[1]), "r"(a[2]), "r"(a[3]), "r"(b0), "r"(b1));
}
__device__ __forceinline__ void cvt_hl4(float4 v, uint2& hv, uint2& lv) {
    __nv_bfloat16 hx = __float2bfloat16(v.x), hy = __float2bfloat16(v.y);
    __nv_bfloat16 hz = __float2bfloat16(v.z), hw = __float2bfloat16(v.w);
    __nv_bfloat16 lx = __float2bfloat16(v.x - __bfloat162float(hx));
    __nv_bfloat16 ly = __float2bfloat16(v.y - __bfloat162float(hy));
    __nv_bfloat16 lz = __float2bfloat16(v.z - __bfloat162float(hz));
    __nv_bfloat16 lw = __float2bfloat16(v.w - __bfloat162float(hw));
    hv.x = ((uint32_t)__bfloat16_as_ushort(hy) << 16) | __bfloat16_as_ushort(hx);
    hv.y = ((uint32_t)__bfloat16_as_ushort(hw) << 16) | __bfloat16_as_ushort(hz);
    lv.x = ((uint32_t)__bfloat16_as_ushort(ly) << 16) | __bfloat16_as_ushort(lx);
    lv.y = ((uint32_t)__bfloat16_as_ushort(lw) << 16) | __bfloat16_as_ushort(lz);
}

// SMEM element-offset layout per buffer (bf16 units). Row stride 24 elements.
constexpr int sAH = 0;              // [2][128][24]
constexpr int sAL = 6144;
constexpr int sBH = 12288;          // [2][64][24]
constexpr int sBL = 15360;
constexpr int SM_ELEMS = 18432;
constexpr int SMEM_BYTES = 2 * SM_ELEMS * 2;   // 73,728 B

// ======== compute phase: one 32-K chunk from a buffer ========
__device__ __forceinline__ void compute_chunk(uint32_t cb, int mrow, int nrow, int g, int r8,
                                              float acc[2][4][4]) {
#pragma unroll
    for (int ks = 0; ks < 2; ks++) {
        uint32_t ah[2][4], al[2][4], bh[2][4], bl[2][4];
#pragma unroll
        for (int mt = 0; mt < 2; mt++) {
            int row = mrow + mt * 16 + (g & 1) * 8 + r8;
            uint32_t bo = (uint32_t)(((ks * 128 + row) * 24 + (g >> 1) * 8) * 2);
            ldsm4(ah[mt], cb + sAH * 2 + bo);
            ldsm4(al[mt], cb + sAL * 2 + bo);
        }
#pragma unroll
        for (int bt = 0; bt < 2; bt++) {
            int row = nrow + bt * 16 + (g >> 1) * 8 + r8;
            uint32_t bo = (uint32_t)(((ks * 64 + row) * 24 + (g & 1) * 8) * 2);
            ldsm4(bh[bt], cb + sBH * 2 + bo);
            ldsm4(bl[bt], cb + sBL * 2 + bo);
        }
#pragma unroll
        for (int mi = 0; mi < 2; mi++)
#pragma unroll
            for (int nj = 0; nj < 4; nj++) {
                int bt = nj >> 1, sub = (nj & 1) * 2;
                mma_bf16(acc[mi][nj], ah[mi], bh[bt][sub], bh[bt][sub + 1]);
                mma_bf16(acc[mi][nj], ah[mi], bl[bt][sub], bl[bt][sub + 1]);
                mma_bf16(acc[mi][nj], al[mi], bh[bt][sub], bh[bt][sub + 1]);
            }
    }
}

// ============ bf16-split HMMA GEMM: AM/BM modes, 2-stage register pipeline ============
// AM: 0 = gA fp32 [M,K], convert in-loop. 1 = gAh/gAl bf16 [M,K] pre-split.
// BM: 0 = gB fp32 [K,N] (NN transpose in STS). 1 = gBh/gBl bf16 [N,K] pre-split.
//     2 = fp32 [N,K] (NT) with row clamp to Bn; source = gB2 if g_flag==0 else gB.
template <int AM, int BM>
__global__ __launch_bounds__(256, 2)
void hgemm(const float* __restrict__ gA,
           const __nv_bfloat16* __restrict__ gAh, const __nv_bfloat16* __restrict__ gAl,
           const float* __restrict__ gB, const float* __restrict__ gB2,
           const __nv_bfloat16* __restrict__ gBh, const __nv_bfloat16* __restrict__ gBl,
           float* __restrict__ gC,
           int M, int Nld, int Kchunks, int lda, int ldb, int Bn, int nsplit, int onlyFallback,
           long sAb, long sBb, long sCb, long sAk, long sBk, long sCk) {
    if (onlyFallback && g_flag == 0) return;
    extern __shared__ __align__(16) uint16_t sm[];
    const int zb = blockIdx.z / nsplit;
    const int zs = blockIdx.z - zb * nsplit;
    if (AM == 0) gA += (long)zb * sAb + (long)zs * sAk;
    else { gAh += (long)zb * sAb + (long)zs * sAk; gAl += (long)zb * sAb + (long)zs * sAk; }
    if (BM == 1) { gBh += (long)zb * sBb + (long)zs * sBk; gBl += (long)zb * sBb + (long)zs * sBk; }
    else if (BM == 0) gB += (long)zb * sBb + (long)zs * sBk;
    else {
        const float* src = (g_flag == 0) ? gB2 : gB;
        gB = src + (long)zb * sBb + (long)zs * sBk;
    }
    gC += (long)zb * sCb + (long)zs * sCk;
    const int m0 = blockIdx.y * 128;
    const int n0 = blockIdx.x * 64;
    const int tid = threadIdx.x;
    const int lane = tid & 31;
    const int w = tid >> 5;
    const int mrow = (w & 3) * 32;
    const int nrow = (w >> 2) * 32;
    const uint32_t sbase = smem_u32(sm);

    float4 ra[4];
    uint4 pah[2], pal[2];
    float4 rbf[2];
    uint4 pbh, pbl;

    int a_r[4], a_j[4];
    if (AM == 0) {
#pragma unroll
        for (int it = 0; it < 4; it++) { int f = it * 256 + tid; a_r[it] = f >> 3; a_j[it] = f & 7; }
    } else {
#pragma unroll
        for (int it = 0; it < 2; it++) { int f = it * 256 + tid; a_r[it] = f >> 2; a_j[it] = f & 3; }
    }
    int b_r[2], b_j[2];
    if (BM == 0) {
#pragma unroll
        for (int it = 0; it < 2; it++) { int f = it * 256 + tid; b_r[it] = f >> 4; b_j[it] = f & 15; }
    } else if (BM == 2) {
#pragma unroll
        for (int it = 0; it < 2; it++) { int f = it * 256 + tid; b_r[it] = f >> 3; b_j[it] = f & 7; }
    } else {
        b_r[0] = tid >> 2; b_j[0] = tid & 3;
    }

    auto loadA = [&](int k0) {
        if (AM == 0) {
#pragma unroll
            for (int it = 0; it < 4; it++) {
                ra[it] = make_float4(0.f, 0.f, 0.f, 0.f);
                if (m0 + a_r[it] < M)
                    ra[it] = *(const float4*)(gA + (long)(m0 + a_r[it]) * lda + k0 + a_j[it] * 4);
            }
        } else {
#pragma unroll
            for (int it = 0; it < 2; it++) {
                pah[it] = make_uint4(0, 0, 0, 0); pal[it] = make_uint4(0, 0, 0, 0);
                if (m0 + a_r[it] < M) {
                    long base = (long)(m0 + a_r[it]) * lda + k0 + a_j[it] * 8;
                    pah[it] = *(const uint4*)(gAh + base);
                    pal[it] = *(const uint4*)(gAl + base);
                }
            }
        }
    };
    auto loadB = [&](int k0) {
        if (BM == 0) {
#pragma unroll
            for (int it = 0; it < 2; it++)
                rbf[it] = *(const float4*)(gB + (long)(k0 + b_r[it]) * ldb + n0 + b_j[it] * 4);
        } else if (BM == 2) {
#pragma unroll
            for (int it = 0; it < 2; it++) {
                int rr = min(n0 + b_r[it], Bn - 1);
                rbf[it] = *(const float4*)(gB + (long)rr * ldb + k0 + b_j[it] * 4);
            }
        } else {
            long base = (long)(n0 + b_r[0]) * ldb + k0 + b_j[0] * 8;
            pbh = *(const uint4*)(gBh + base);
            pbl = *(const uint4*)(gBl + base);
        }
    };
    auto storeA = [&](uint16_t* bp) {
        if (AM == 0) {
#pragma unroll
            for (int it = 0; it < 4; it++) {
                uint2 hv, lv;
                cvt_hl4(ra[it], hv, lv);
                int off = (((a_j[it] >> 2) * 128 + a_r[it]) * 24) + (a_j[it] & 3) * 4;
                *(uint2*)&bp[sAH + off] = hv;
                *(uint2*)&bp[sAL + off] = lv;
            }
        } else {
#pragma unroll
            for (int it = 0; it < 2; it++) {
                int off = (((a_j[it] >> 1) * 128 + a_r[it]) * 24) + (a_j[it] & 1) * 8;
                *(uint4*)&bp[sAH + off] = pah[it];
                *(uint4*)&bp[sAL + off] = pal[it];
            }
        }
    };
    auto storeB = [&](uint16_t* bp) {
        if (BM == 0) {
#pragma unroll
            for (int it = 0; it < 2; it++) {
                float vv[4] = {rbf[it].x, rbf[it].y, rbf[it].z, rbf[it].w};
                int h = b_r[it] >> 4, kk = b_r[it] & 15;
#pragma unroll
                for (int e = 0; e < 4; e++) {
                    int n = b_j[it] * 4 + e;
                    __nv_bfloat16 hb = __float2bfloat16(vv[e]);
                    __nv_bfloat16 lb = __float2bfloat16(vv[e] - __bfloat162float(hb));
                    int off = ((h * 64 + n) * 24) + kk;
                    bp[sBH + off] = __bfloat16_as_ushort(hb);
                    bp[sBL + off] = __bfloat16_as_ushort(lb);
                }
            }
        } else if (BM == 2) {
#pragma unroll
            for (int it = 0; it < 2; it++) {
                uint2 hv, lv;
                cvt_hl4(rbf[it], hv, lv);
                int off = (((b_j[it] >> 2) * 64 + b_r[it]) * 24) + (b_j[it] & 3) * 4;
                *(uint2*)&bp[sBH + off] = hv;
                *(uint2*)&bp[sBL + off] = lv;
            }
        } else {
            int off = (((b_j[0] >> 1) * 64 + b_r[0]) * 24) + (b_j[0] & 1) * 8;
            *(uint4*)&bp[sBH + off] = pbh;
            *(uint4*)&bp[sBL + off] = pbl;
        }
    };

    float acc[2][4][4];
#pragma unroll
    for (int i = 0; i < 2; i++)
#pragma unroll
        for (int j = 0; j < 4; j++)
#pragma unroll
            for (int q = 0; q < 4; q++) acc[i][j][q] = 0.f;

    const int g = lane >> 3, r8 = lane & 7;

    loadA(0); loadB(0);
    storeA(sm); storeB(sm);
    __syncthreads();
    if (Kchunks > 1) { loadA(32); loadB(32); }

    for (int c = 0; c < Kchunks; c++) {
        if (c + 1 < Kchunks) {
            uint16_t* bp = sm + ((c + 1) & 1) * SM_ELEMS;
            storeA(bp); storeB(bp);
        }
        if (c + 2 < Kchunks) { loadA((c + 2) * 32); loadB((c + 2) * 32); }
        compute_chunk(sbase + (uint32_t)((c & 1) * SM_ELEMS * 2), mrow, nrow, g, r8, acc);
        __syncthreads();
    }

#pragma unroll
    for (int mi = 0; mi < 2; mi++) {
        int rg = m0 + mrow + mi * 16 + (lane >> 2);
#pragma unroll
        for (int nj = 0; nj < 4; nj++) {
            int cg = n0 + nrow + nj * 8 + 2 * (lane & 3);
            if (rg < M) {
                *(float2*)(gC + (long)rg * Nld + cg) = make_float2(acc[mi][nj][0], acc[mi][nj][1]);
            }
            if (rg + 8 < M) {
                *(float2*)(gC + (long)(rg + 8) * Nld + cg) = make_float2(acc[mi][nj][2], acc[mi][nj][3]);
            }
        }
    }
}

// ---------------- flag init + identity check ----------------
__global__ void init_flag_kernel() { g_flag = 0; }

__global__ void check_identity(const float* __restrict__ Wbil) {
    long idx = (long)blockIdx.x * blockDim.x + threadIdx.x;
    if (idx >= (long)cD * cD / 4) return;
    long e0 = idx * 4;
    int r = (int)(e0 >> 11);
    int c = (int)(e0 & 2047);
    float4 v = *(const float4*)(Wbil + e0);
    float vv[4] = {v.x, v.y, v.z, v.w};
    bool bad = false;
#pragma unroll
    for (int q = 0; q < 4; q++) {
        float want = (r == c + q) ? 1.f : 0.f;
        if (vv[q] != want) bad = true;
    }
    if (bad) atomicOr(&g_flag, 1);
}

// ---------------- fp32 -> bf16 hi/lo split convert ----------------
__global__ void conv_split(const float* __restrict__ src,
                           __nv_bfloat16* __restrict__ H, __nv_bfloat16* __restrict__ L, long n4) {
    long idx = (long)blockIdx.x * blockDim.x + threadIdx.x;
    if (idx >= n4) return;
    float4 v = *(const float4*)(src + idx * 4);
    uint2 hv, lv;
    cvt_hl4(v, hv, lv);
    *(uint2*)(H + idx * 4) = hv;
    *(uint2*)(L + idx * 4) = lv;
}

// ---------------- W [Krows, H] -> Wt hi/lo [H, Krows] ----------------
__global__ void transpose_w(const float* __restrict__ W,
                            __nv_bfloat16* __restrict__ Th, __nv_bfloat16* __restrict__ Tl,
                            int outLd) {
    __shared__ float s[32][33];
    int n0 = blockIdx.x * 32;
    int k0 = blockIdx.y * 32;
    int tx = threadIdx.x & 31, ty = threadIdx.x >> 5;
#pragma unroll
    for (int i = 0; i < 4; i++)
        s[ty + 8 * i][tx] = W[(long)(k0 + ty + 8 * i) * cH + n0 + tx];
    __syncthreads();
#pragma unroll
    for (int i = 0; i < 4; i++) {
        float v = s[tx][ty + 8 * i];
        __nv_bfloat16 h = __float2bfloat16(v);
        __nv_bfloat16 l = __float2bfloat16(v - __bfloat162float(h));
        long o = (long)(n0 + ty + 8 * i) * outLd + k0 + tx;
        Th[o] = h; Tl[o] = l;
    }
}

// ---------------- ft @ W1_top partials ----------------
__global__ void ft_contrib(const float* __restrict__ ft, const float* __restrict__ W1,
                           float* __restrict__ Hbp) {
    __shared__ float sf[cB * 64];
    int jx = blockIdx.x * 128 + threadIdx.x;
    int s = blockIdx.y;
    int k0 = s * 64;
    for (int i = threadIdx.x; i < cB * 64; i += 128) {
        int b = i >> 6, k = i & 63;
        sf[i] = ft[(long)b * cD + k0 + k];
    }
    __syncthreads();
    float acc[cB];
#pragma unroll
    for (int b = 0; b < cB; b++) acc[b] = 0.f;
#pragma unroll
    for (int kk = 0; kk < 64; kk += 8) {
        float wv[8];
#pragma unroll
        for (int u = 0; u < 8; u++)
            wv[u] = W1[(long)(k0 + kk + u) * cH + jx];
#pragma unroll
        for (int u = 0; u < 8; u++)
#pragma unroll
            for (int b = 0; b < cB; b++) acc[b] += sf[b * 64 + kk + u] * wv[u];
    }
#pragma unroll
    for (int b = 0; b < cB; b++)
        Hbp[(long)s * cB * cH + (long)b * cH + jx] = acc[b];
}

__global__ void ft_sum(const float* __restrict__ Hbp, float* __restrict__ Hbs) {
    int idx = blockIdx.x * 256 + threadIdx.x;
    if (idx >= cB * cH) return;
    float s = 0.f;
#pragma unroll
    for (int p = 0; p < FT_SPLIT; p++) s += Hbp[(long)p * cB * cH + idx];
    Hbs[idx] = s;
}

__global__ void tproj_reduce(const float* __restrict__ P, float* __restrict__ tp) {
    if (g_flag == 0) return;
    long idx = (long)blockIdx.x * blockDim.x + threadIdx.x;
    const long n4 = (long)cB * cX * cD / 4;
    if (idx >= n4) return;
    float4 a = *(const float4*)(P + idx * 4);
    float4 b = *(const float4*)(P + n4 * 4 + idx * 4);
    *(float4*)(&tp[idx * 4]) = make_float4(a.x + b.x, a.y + b.y, a.z + b.z, a.w + b.w);
}

// ---------------- MLP tail (rowBase for group pipelining) ----------------
__global__ void mlp_reduce(const float* __restrict__ Hp, const float* __restrict__ b1,
                           const float* __restrict__ W2, const float* __restrict__ b2,
                           float* __restrict__ scores, int accumulate,
                           const float* __restrict__ Hb, int rowBase) {
    int row = rowBase + blockIdx.x;
    int b = row >> 5;
    int tid = threadIdx.x;
    float s = 0.f;
    for (int j = tid; j < cH; j += 256) {
        float h = b1[j];
#pragma unroll
        for (int p = 0; p < MLP_SPLIT; p++) h += Hp[(long)p * ROWS * cH + (long)row * cH + j];
        if (Hb) h += Hb[(long)b * cH + j];
        h = fmaxf(h, 0.f);
        s += h * W2[j];
    }
    __shared__ float red[256];
    red[tid] = s;
    __syncthreads();
    for (int o = 128; o > 0; o >>= 1) {
        if (tid < o) red[tid] += red[tid + o];
        __syncthreads();
    }
    if (tid == 0) {
        float v = red[0] + b2[0];
        if (accumulate) scores[row] += v;
        else scores[row] = v;
    }
}

// ---------------- attention pooling per (b,i) -> X2 bf16 hi/lo ----------------
__global__ void attn_kernel(const float* __restrict__ inners,
                            const int* __restrict__ mt, const int* __restrict__ md,
                            const float* __restrict__ att_t, const float* __restrict__ att_d,
                            __nv_bfloat16* __restrict__ X2h, __nv_bfloat16* __restrict__ X2l,
                            int biBase) {
    int bi = biBase + blockIdx.x;
    int b = bi >> 5;
    int i = bi & 31;
    __shared__ float S[cX][cX];
    __shared__ float tw[cX], dw[cX];
    int tid = threadIdx.x;
    const long PS = (long)cB * cN * cX * 64;

    for (int idx = tid; idx < cX * cX; idx += 256) {
        int x = idx / cX, y = idx % cX;
        long o = ((long)b * (cN * cX) + i * cX + y) * 64 + x;
        float v = 0.f;
#pragma unroll
        for (int p = 0; p < INN_SPLIT; p++) v += inners[p * PS + o];
        int mm = mt[b * cX + x] * md[(b * cN + i) * cX + y];
        S[x][y] = (mm > 0) ? v : BIG_NEG_F;
    }
    __syncthreads();

    if (tid < cX) {
        float mx = -3.4e38f;
        for (int y = 0; y < cX; y++) mx = fmaxf(mx, S[tid][y]);
        tw[tid] = mx;
    } else if (tid < 2 * cX) {
        int y = tid - cX;
        float mx = -3.4e38f;
        for (int x = 0; x < cX; x++) mx = fmaxf(mx, S[x][y]);
        dw[y] = mx;
    }
    __syncthreads();

    if (tid == 0) {
        float m = -3.4e38f;
        for (int x = 0; x < cX; x++) m = fmaxf(m, tw[x]);
        float s = 0.f;
        for (int x = 0; x < cX; x++) { float e = expf(tw[x] - m); tw[x] = e; s += e; }
        float inv = 1.f / s;
        for (int x = 0; x < cX; x++) tw[x] *= inv;
    }
    if (tid == 32) {
        float m = -3.4e38f;
        for (int y = 0; y < cX; y++) m = fmaxf(m, dw[y]);
        float s = 0.f;
        for (int y = 0; y < cX; y++) { float e = expf(dw[y] - m); dw[y] = e; s += e; }
        float inv = 1.f / s;
        for (int y = 0; y < cX; y++) dw[y] *= inv;
    }
    __syncthreads();

    const float* tb = att_t + (long)b * cX * cD;
    const float* db = att_d + (long)(b * cN + i) * cX * cD;
    for (int d = tid; d < cD; d += 256) {
        float tf = 0.f, df = 0.f;
#pragma unroll
        for (int x = 0; x < cX; x++) {
            tf += tw[x] * tb[(long)x * cD + d];
            df += dw[x] * db[(long)x * cD + d];
        }
        __nv_bfloat16 th = __float2bfloat16(tf);
        __nv_bfloat16 tl = __float2bfloat16(tf - __bfloat162float(th));
        __nv_bfloat16 dh = __float2bfloat16(df);
        __nv_bfloat16 dl = __float2bfloat16(df - __bfloat162float(dh));
        long o = (long)bi * K2 + d;
        X2h[o] = th; X2l[o] = tl;
        X2h[o + cD] = dh; X2l[o + cD] = dl;
    }
}

// ---------------- final log_softmax ----------------
__global__ void logsoftmax_kernel(const float* __restrict__ scores, float* __restrict__ out) {
    int b = blockIdx.x;
    int n = threadIdx.x;
    float v = scores[b * cN + n];
    float m = v;
    for (int o = 16; o > 0; o >>= 1) m = fmaxf(m, __shfl_xor_sync(0xffffffffu, m, o));
    float e = expf(v - m);
    float s = e;
    for (int o = 16; o > 0; o >>= 1) s += __shfl_xor_sync(0xffffffffu, s, o);
    out[b * cN + n] = v - m - logf(s);
}

// ---------------- host ----------------
extern "C" void kernel_launch(void* const* d_in, const int* in_sizes, int n_in,
                              void* d_out, int out_size) {
    const float* fc_t = (const float*)d_in[0];
    const float* fc_d = (const float*)d_in[1];
    const float* att_t = (const float*)d_in[2];
    const float* att_d = (const float*)d_in[3];
    const int* am_t = (const int*)d_in[4];
    const int* am_d = (const int*)d_in[5];
    const float* W1 = (const float*)d_in[6];
    const float* b1 = (const float*)d_in[7];
    const float* W2 = (const float*)d_in[8];
    const float* b2 = (const float*)d_in[9];
    const float* Wbil = (const float*)d_in[10];
    const float* oW1 = (const float*)d_in[11];
    const float* ob1 = (const float*)d_in[12];
    const float* oW2 = (const float*)d_in[13];
    const float* ob2 = (const float*)d_in[14];
    float* out = (float*)d_out;

    float *Hp, *Hb, *Hbs, *tproj, *tprojP, *inn, *scores;
    __nv_bfloat16 *fdh, *fdl, *X2h, *X2l, *Wt1h, *Wt1l, *Wt2h, *Wt2l;
    cudaGetSymbolAddress((void**)&Hp, g_Hpart);
    cudaGetSymbolAddress((void**)&Hb, g_Hb);
    cudaGetSymbolAddress((void**)&Hbs, g_Hbs);
    cudaGetSymbolAddress((void**)&tproj, g_tproj);
    cudaGetSymbolAddress((void**)&tprojP, g_tprojP);
    cudaGetSymbolAddress((void**)&inn, g_inners);
    cudaGetSymbolAddress((void**)&scores, g_scores);
    cudaGetSymbolAddress((void**)&fdh, g_fdh);
    cudaGetSymbolAddress((void**)&fdl, g_fdl);
    cudaGetSymbolAddress((void**)&X2h, g_X2h);
    cudaGetSymbolAddress((void**)&X2l, g_X2l);
    cudaGetSymbolAddress((void**)&Wt1h, g_Wt1h);
    cudaGetSymbolAddress((void**)&Wt1l, g_Wt1l);
    cudaGetSymbolAddress((void**)&Wt2h, g_Wt2h);
    cudaGetSymbolAddress((void**)&Wt2l, g_Wt2l);

    static cudaStream_t s1 = nullptr, s2 = nullptr;
    static cudaEvent_t evFork = nullptr, evJoin = nullptr, evTp = nullptr, evG1 = nullptr;
    if (s1 == nullptr) {
        cudaStreamCreateWithFlags(&s1, cudaStreamNonBlocking);
        cudaStreamCreateWithFlags(&s2, cudaStreamNonBlocking);
        cudaEventCreateWithFlags(&evFork, cudaEventDisableTiming);
        cudaEventCreateWithFlags(&evJoin, cudaEventDisableTiming);
        cudaEventCreateWithFlags(&evTp, cudaEventDisableTiming);
        cudaEventCreateWithFlags(&evG1, cudaEventDisableTiming);
        cudaFuncSetAttribute((const void*)hgemm<0, 0>, cudaFuncAttributeMaxDynamicSharedMemorySize, SMEM_BYTES);
        cudaFuncSetAttribute((const void*)hgemm<0, 2>, cudaFuncAttributeMaxDynamicSharedMemorySize, SMEM_BYTES);
        cudaFuncSetAttribute((const void*)hgemm<1, 1>, cudaFuncAttributeMaxDynamicSharedMemorySize, SMEM_BYTES);
    }

    // ---- fork: stream1 runs the independent base-score chain ----
    cudaEventRecord(evFork, 0);
    cudaStreamWaitEvent(s1, evFork, 0);
    cudaStreamWaitEvent(s2, evFork, 0);

    // [stream1] base-score chain + oW1 transpose
    conv_split<<<(ROWS * cD / 4 + 255) / 256, 256, 0, s1>>>(fc_d, fdh, fdl, (long)ROWS * cD / 4);
    transpose_w<<<dim3(cH / 32, cD / 32), 256, 0, s1>>>(W1 + (long)cD * cH, Wt1h, Wt1l, cD);
    transpose_w<<<dim3(cH / 32, K2 / 32), 256, 0, s1>>>(oW1, Wt2h, Wt2l, K2);
    ft_contrib<<<dim3(cH / 128, FT_SPLIT), 128, 0, s1>>>(fc_t, W1, Hb);
    ft_sum<<<(cB * cH + 255) / 256, 256, 0, s1>>>(Hb, Hbs);
    hgemm<1, 1><<<dim3(cH / 64, ROWS / 128, MLP_SPLIT), 256, SMEM_BYTES, s1>>>(
        nullptr, fdh, fdl, nullptr, nullptr, Wt1h, Wt1l, Hp,
        ROWS, cH, (cD / MLP_SPLIT) / 32, cD, cD, cH, MLP_SPLIT, 0,
        0, 0, 0, (long)(cD / MLP_SPLIT), (long)(cD / MLP_SPLIT), (long)ROWS * cH);
    mlp_reduce<<<ROWS, 256, 0, s1>>>(Hp, b1, W2, b2, scores, 0, Hbs, 0);
    cudaEventRecord(evJoin, s1);

    // [default stream] flag + tproj fallback (shared by both groups)
    init_flag_kernel<<<1, 1>>>();
    check_identity<<<(cD * cD / 4 + 255) / 256, 256>>>(Wbil);
    hgemm<0, 0><<<dim3(cD / 64, (cB * cX + 127) / 128, 2), 256, SMEM_BYTES>>>(
        att_t, nullptr, nullptr, Wbil, nullptr, nullptr, nullptr, tprojP,
        cB * cX, cD, (cD / 2) / 32, cD, cD, cD, 2, 1,
        0, 0, 0, (long)(cD / 2), (long)(cD / 2) * cD, (long)cB * cX * cD);
    tproj_reduce<<<(cB * cX * cD / 4 + 255) / 256, 256>>>(tprojP, tproj);
    cudaEventRecord(evTp, 0);
    cudaStreamWaitEvent(s2, evTp, 0);

    // ---- pipelined batch groups: g0 on default stream, g1 on s2 ----
    const long AD_B = (long)cN * cX * cD;       // att_d per-batch stride
    const long TP_B = (long)cX * cD;            // tproj/att_t per-batch stride
    const long IN_B = (long)cN * cX * 64;       // inners per-batch stride
    for (int grp = 0; grp < NGRP; grp++) {
        cudaStream_t st = (grp == 0) ? (cudaStream_t)0 : s2;
        const long bo = (long)grp * GB;
        // inners for this group's GB batches, K-split x INN_SPLIT
        hgemm<0, 2><<<dim3(1, (cN * cX) / 128, GB * INN_SPLIT), 256, SMEM_BYTES, st>>>(
            att_d + bo * AD_B, nullptr, nullptr, tproj + bo * TP_B, att_t + bo * TP_B,
            nullptr, nullptr, inn + bo * IN_B,
            cN * cX, 64, (cD / INN_SPLIT) / 32, cD, cD, cX, INN_SPLIT, 0,
            AD_B, TP_B, IN_B,
            (long)(cD / INN_SPLIT), (long)(cD / INN_SPLIT), (long)cB * cN * cX * 64);
        // attention pooling for this group's 256 (b,i) rows
        attn_kernel<<<GB * cN, 256, 0, st>>>(inn, am_t, am_d, att_t, att_d, X2h, X2l,
                                             (int)(bo * cN));
        // object MLP for this group's 256 rows (needs Wt2 + base scores from s1)
        cudaStreamWaitEvent(st, evJoin, 0);
        hgemm<1, 1><<<dim3(cH / 64, (GB * cN) / 128, MLP_SPLIT), 256, SMEM_BYTES, st>>>(
            nullptr, X2h + bo * cN * K2, X2l + bo * cN * K2, nullptr, nullptr, Wt2h, Wt2l,
            Hp + bo * cN * cH,
            GB * cN, cH, (K2 / MLP_SPLIT) / 32, K2, K2, cH, MLP_SPLIT, 0,
            0, 0, 0, (long)(K2 / MLP_SPLIT), (long)(K2 / MLP_SPLIT), (long)ROWS * cH);
        mlp_reduce<<<GB * cN, 256, 0, st>>>(Hp, ob1, oW2, ob2, scores, 1, nullptr,
                                            (int)(bo * cN));
    }
    cudaEventRecord(evG1, s2);
    cudaStreamWaitEvent(0, evG1, 0);

    logsoftmax_kernel<<<cB, 32>>>(scores, out);
}

// round 15
// speedup vs baseline: 1.3033x; 1.1954x over previous
#include <cuda_runtime.h>
#include <cuda_bf16.h>
#include <math.h>
#include <stdint.h>

// Problem constants
constexpr int cB = 16;
constexpr int cN = 32;
constexpr int cX = 36;
constexpr int cD = 2048;
constexpr int cH = 512;
constexpr int ROWS = cB * cN;     // 512
constexpr int K2 = 2 * cD;        // 4096
constexpr int MLP_SPLIT = 8;
constexpr int INN_SPLIT = 2;
constexpr int FT_SPLIT = 32;
constexpr int NGRP = 4;           // batch groups for pipelining
constexpr int GB = cB / NGRP;     // 4 batches per group
#define BIG_NEG_F (-1000000000.0f)

// ---------------- scratch ----------------
__device__ __nv_bfloat16 g_fdh[ROWS * cD], g_fdl[ROWS * cD];
__device__ __nv_bfloat16 g_X2h[ROWS * K2], g_X2l[ROWS * K2];
__device__ __nv_bfloat16 g_Wt1h[cH * cD], g_Wt1l[cH * cD];
__device__ __nv_bfloat16 g_Wt2h[cH * K2], g_Wt2l[cH * K2];
__device__ float g_Hb[FT_SPLIT * cB * cH];
__device__ float g_Hbs[cB * cH];
__device__ float g_Hpart[MLP_SPLIT * ROWS * cH];
__device__ float g_tproj[cB * cX * cD];
__device__ float g_tprojP[2 * cB * cX * cD];
__device__ float g_inners[INN_SPLIT * cB * cN * cX * 64];
__device__ float g_scores[ROWS];
__device__ int g_flag;   // 0 = Wbil identity, 1 = general

// ---------------- helpers ----------------
__device__ __forceinline__ uint32_t smem_u32(const void* p) {
    uint32_t a;
    asm("{ .reg .u64 t; cvta.to.shared.u64 t, %1; cvt.u32.u64 %0, t; }" : "=r"(a) : "l"(p));
    return a;
}
__device__ __forceinline__ void ldsm4(uint32_t* r, uint32_t addr) {
    asm volatile("ldmatrix.sync.aligned.m8n8.x4.shared.b16 {%0,%1,%2,%3}, [%4];"
                 : "=r"(r[0]), "=r"(r[1]), "=r"(r[2]), "=r"(r[3]) : "r"(addr));
}
__device__ __forceinline__ void mma_bf16(float* c, const uint32_t* a, uint32_t b0, uint32_t b1) {
    asm volatile("mma.sync.aligned.m16n8k16.row.col.f32.bf16.bf16.f32 "
                 "{%0,%1,%2,%3}, {%4,%5,%6,%7}, {%8,%9}, {%0,%1,%2,%3};"
                 : "+f"(c[0]), "+f"(c[1]), "+f"(c[2]), "+f"(c[3])
                 : "r"(a[0]), "r"(a[1]), "r"(a[2]), "r"(a[3]), "r"(b0), "r"(b1));
}
__device__ __forceinline__ void cvt_hl4(float4 v, uint2& hv, uint2& lv) {
    __nv_bfloat16 hx = __float2bfloat16(v.x), hy = __float2bfloat16(v.y);
    __nv_bfloat16 hz = __float2bfloat16(v.z), hw = __float2bfloat16(v.w);
    __nv_bfloat16 lx = __float2bfloat16(v.x - __bfloat162float(hx));
    __nv_bfloat16 ly = __float2bfloat16(v.y - __bfloat162float(hy));
    __nv_bfloat16 lz = __float2bfloat16(v.z - __bfloat162float(hz));
    __nv_bfloat16 lw = __float2bfloat16(v.w - __bfloat162float(hw));
    hv.x = ((uint32_t)__bfloat16_as_ushort(hy) << 16) | __bfloat16_as_ushort(hx);
    hv.y = ((uint32_t)__bfloat16_as_ushort(hw) << 16) | __bfloat16_as_ushort(hz);
    lv.x = ((uint32_t)__bfloat16_as_ushort(ly) << 16) | __bfloat16_as_ushort(lx);
    lv.y = ((uint32_t)__bfloat16_as_ushort(lw) << 16) | __bfloat16_as_ushort(lz);
}

// SMEM element-offset layout per buffer (bf16 units). Row stride 24 elements.
constexpr int sAH = 0;              // [2][128][24]
constexpr int sAL = 6144;
constexpr int sBH = 12288;          // [2][64][24]
constexpr int sBL = 15360;
constexpr int SM_ELEMS = 18432;
constexpr int SMEM_BYTES = 2 * SM_ELEMS * 2;   // 73,728 B

// ======== compute phase: one 32-K chunk from a buffer ========
__device__ __forceinline__ void compute_chunk(uint32_t cb, int mrow, int nrow, int g, int r8,
                                              float acc[2][4][4]) {
#pragma unroll
    for (int ks = 0; ks < 2; ks++) {
        uint32_t ah[2][4], al[2][4], bh[2][4], bl[2][4];
#pragma unroll
        for (int mt = 0; mt < 2; mt++) {
            int row = mrow + mt * 16 + (g & 1) * 8 + r8;
            uint32_t bo = (uint32_t)(((ks * 128 + row) * 24 + (g >> 1) * 8) * 2);
            ldsm4(ah[mt], cb + sAH * 2 + bo);
            ldsm4(al[mt], cb + sAL * 2 + bo);
        }
#pragma unroll
        for (int bt = 0; bt < 2; bt++) {
            int row = nrow + bt * 16 + (g >> 1) * 8 + r8;
            uint32_t bo = (uint32_t)(((ks * 64 + row) * 24 + (g & 1) * 8) * 2);
            ldsm4(bh[bt], cb + sBH * 2 + bo);
            ldsm4(bl[bt], cb + sBL * 2 + bo);
        }
#pragma unroll
        for (int mi = 0; mi < 2; mi++)
#pragma unroll
            for (int nj = 0; nj < 4; nj++) {
                int bt = nj >> 1, sub = (nj & 1) * 2;
                mma_bf16(acc[mi][nj], ah[mi], bh[bt][sub], bh[bt][sub + 1]);
                mma_bf16(acc[mi][nj], ah[mi], bl[bt][sub], bl[bt][sub + 1]);
                mma_bf16(acc[mi][nj], al[mi], bh[bt][sub], bh[bt][sub + 1]);
            }
    }
}

// ============ bf16-split HMMA GEMM: AM/BM modes, 2-stage register pipeline ============
// AM: 0 = gA fp32 [M,K], convert in-loop. 1 = gAh/gAl bf16 [M,K] pre-split.
// BM: 0 = gB fp32 [K,N] (NN transpose in STS). 1 = gBh/gBl bf16 [N,K] pre-split.
//     2 = fp32 [N,K] (NT) with row clamp to Bn; source = gB2 if g_flag==0 else gB.
template <int AM, int BM>
__global__ __launch_bounds__(256, 2)
void hgemm(const float* __restrict__ gA,
           const __nv_bfloat16* __restrict__ gAh, const __nv_bfloat16* __restrict__ gAl,
           const float* __restrict__ gB, const float* __restrict__ gB2,
           const __nv_bfloat16* __restrict__ gBh, const __nv_bfloat16* __restrict__ gBl,
           float* __restrict__ gC,
           int M, int Nld, int Kchunks, int lda, int ldb, int Bn, int nsplit, int onlyFallback,
           long sAb, long sBb, long sCb, long sAk, long sBk, long sCk) {
    if (onlyFallback && g_flag == 0) return;
    extern __shared__ __align__(16) uint16_t sm[];
    const int zb = blockIdx.z / nsplit;
    const int zs = blockIdx.z - zb * nsplit;
    if (AM == 0) gA += (long)zb * sAb + (long)zs * sAk;
    else { gAh += (long)zb * sAb + (long)zs * sAk; gAl += (long)zb * sAb + (long)zs * sAk; }
    if (BM == 1) { gBh += (long)zb * sBb + (long)zs * sBk; gBl += (long)zb * sBb + (long)zs * sBk; }
    else if (BM == 0) gB += (long)zb * sBb + (long)zs * sBk;
    else {
        const float* src = (g_flag == 0) ? gB2 : gB;
        gB = src + (long)zb * sBb + (long)zs * sBk;
    }
    gC += (long)zb * sCb + (long)zs * sCk;
    const int m0 = blockIdx.y * 128;
    const int n0 = blockIdx.x * 64;
    const int tid = threadIdx.x;
    const int lane = tid & 31;
    const int w = tid >> 5;
    const int mrow = (w & 3) * 32;
    const int nrow = (w >> 2) * 32;
    const uint32_t sbase = smem_u32(sm);

    float4 ra[4];
    uint4 pah[2], pal[2];
    float4 rbf[2];
    uint4 pbh, pbl;

    int a_r[4], a_j[4];
    if (AM == 0) {
#pragma unroll
        for (int it = 0; it < 4; it++) { int f = it * 256 + tid; a_r[it] = f >> 3; a_j[it] = f & 7; }
    } else {
#pragma unroll
        for (int it = 0; it < 2; it++) { int f = it * 256 + tid; a_r[it] = f >> 2; a_j[it] = f & 3; }
    }
    int b_r[2], b_j[2];
    if (BM == 0) {
#pragma unroll
        for (int it = 0; it < 2; it++) { int f = it * 256 + tid; b_r[it] = f >> 4; b_j[it] = f & 15; }
    } else if (BM == 2) {
#pragma unroll
        for (int it = 0; it < 2; it++) { int f = it * 256 + tid; b_r[it] = f >> 3; b_j[it] = f & 7; }
    } else {
        b_r[0] = tid >> 2; b_j[0] = tid & 3;
    }

    auto loadA = [&](int k0) {
        if (AM == 0) {
#pragma unroll
            for (int it = 0; it < 4; it++) {
                ra[it] = make_float4(0.f, 0.f, 0.f, 0.f);
                if (m0 + a_r[it] < M)
                    ra[it] = *(const float4*)(gA + (long)(m0 + a_r[it]) * lda + k0 + a_j[it] * 4);
            }
        } else {
#pragma unroll
            for (int it = 0; it < 2; it++) {
                pah[it] = make_uint4(0, 0, 0, 0); pal[it] = make_uint4(0, 0, 0, 0);
                if (m0 + a_r[it] < M) {
                    long base = (long)(m0 + a_r[it]) * lda + k0 + a_j[it] * 8;
                    pah[it] = *(const uint4*)(gAh + base);
                    pal[it] = *(const uint4*)(gAl + base);
                }
            }
        }
    };
    auto loadB = [&](int k0) {
        if (BM == 0) {
#pragma unroll
            for (int it = 0; it < 2; it++)
                rbf[it] = *(const float4*)(gB + (long)(k0 + b_r[it]) * ldb + n0 + b_j[it] * 4);
        } else if (BM == 2) {
#pragma unroll
            for (int it = 0; it < 2; it++) {
                int rr = min(n0 + b_r[it], Bn - 1);
                rbf[it] = *(const float4*)(gB + (long)rr * ldb + k0 + b_j[it] * 4);
            }
        } else {
            long base = (long)(n0 + b_r[0]) * ldb + k0 + b_j[0] * 8;
            pbh = *(const uint4*)(gBh + base);
            pbl = *(const uint4*)(gBl + base);
        }
    };
    auto storeA = [&](uint16_t* bp) {
        if (AM == 0) {
#pragma unroll
            for (int it = 0; it < 4; it++) {
                uint2 hv, lv;
                cvt_hl4(ra[it], hv, lv);
                int off = (((a_j[it] >> 2) * 128 + a_r[it]) * 24) + (a_j[it] & 3) * 4;
                *(uint2*)&bp[sAH + off] = hv;
                *(uint2*)&bp[sAL + off] = lv;
            }
        } else {
#pragma unroll
            for (int it = 0; it < 2; it++) {
                int off = (((a_j[it] >> 1) * 128 + a_r[it]) * 24) + (a_j[it] & 1) * 8;
                *(uint4*)&bp[sAH + off] = pah[it];
                *(uint4*)&bp[sAL + off] = pal[it];
            }
        }
    };
    auto storeB = [&](uint16_t* bp) {
        if (BM == 0) {
#pragma unroll
            for (int it = 0; it < 2; it++) {
                float vv[4] = {rbf[it].x, rbf[it].y, rbf[it].z, rbf[it].w};
                int h = b_r[it] >> 4, kk = b_r[it] & 15;
#pragma unroll
                for (int e = 0; e < 4; e++) {
                    int n = b_j[it] * 4 + e;
                    __nv_bfloat16 hb = __float2bfloat16(vv[e]);
                    __nv_bfloat16 lb = __float2bfloat16(vv[e] - __bfloat162float(hb));
                    int off = ((h * 64 + n) * 24) + kk;
                    bp[sBH + off] = __bfloat16_as_ushort(hb);
                    bp[sBL + off] = __bfloat16_as_ushort(lb);
                }
            }
        } else if (BM == 2) {
#pragma unroll
            for (int it = 0; it < 2; it++) {
                uint2 hv, lv;
                cvt_hl4(rbf[it], hv, lv);
                int off = (((b_j[it] >> 2) * 64 + b_r[it]) * 24) + (b_j[it] & 3) * 4;
                *(uint2*)&bp[sBH + off] = hv;
                *(uint2*)&bp[sBL + off] = lv;
            }
        } else {
            int off = (((b_j[0] >> 1) * 64 + b_r[0]) * 24) + (b_j[0] & 1) * 8;
            *(uint4*)&bp[sBH + off] = pbh;
            *(uint4*)&bp[sBL + off] = pbl;
        }
    };

    float acc[2][4][4];
#pragma unroll
    for (int i = 0; i < 2; i++)
#pragma unroll
        for (int j = 0; j < 4; j++)
#pragma unroll
            for (int q = 0; q < 4; q++) acc[i][j][q] = 0.f;

    const int g = lane >> 3, r8 = lane & 7;

    loadA(0); loadB(0);
    storeA(sm); storeB(sm);
    __syncthreads();
    if (Kchunks > 1) { loadA(32); loadB(32); }

    for (int c = 0; c < Kchunks; c++) {
        if (c + 1 < Kchunks) {
            uint16_t* bp = sm + ((c + 1) & 1) * SM_ELEMS;
            storeA(bp); storeB(bp);
        }
        if (c + 2 < Kchunks) { loadA((c + 2) * 32); loadB((c + 2) * 32); }
        compute_chunk(sbase + (uint32_t)((c & 1) * SM_ELEMS * 2), mrow, nrow, g, r8, acc);
        __syncthreads();
    }

#pragma unroll
    for (int mi = 0; mi < 2; mi++) {
        int rg = m0 + mrow + mi * 16 + (lane >> 2);
#pragma unroll
        for (int nj = 0; nj < 4; nj++) {
            int cg = n0 + nrow + nj * 8 + 2 * (lane & 3);
            if (rg < M) {
                *(float2*)(gC + (long)rg * Nld + cg) = make_float2(acc[mi][nj][0], acc[mi][nj][1]);
            }
            if (rg + 8 < M) {
                *(float2*)(gC + (long)(rg + 8) * Nld + cg) = make_float2(acc[mi][nj][2], acc[mi][nj][3]);
            }
        }
    }
}

// ---------------- flag init + identity check ----------------
__global__ void init_flag_kernel() { g_flag = 0; }

__global__ void check_identity(const float* __restrict__ Wbil) {
    long idx = (long)blockIdx.x * blockDim.x + threadIdx.x;
    if (idx >= (long)cD * cD / 4) return;
    long e0 = idx * 4;
    int r = (int)(e0 >> 11);
    int c = (int)(e0 & 2047);
    float4 v = *(const float4*)(Wbil + e0);
    float vv[4] = {v.x, v.y, v.z, v.w};
    bool bad = false;
#pragma unroll
    for (int q = 0; q < 4; q++) {
        float want = (r == c + q) ? 1.f : 0.f;
        if (vv[q] != want) bad = true;
    }
    if (bad) atomicOr(&g_flag, 1);
}

// ---------------- fp32 -> bf16 hi/lo split convert ----------------
__global__ void conv_split(const float* __restrict__ src,
                           __nv_bfloat16* __restrict__ H, __nv_bfloat16* __restrict__ L, long n4) {
    long idx = (long)blockIdx.x * blockDim.x + threadIdx.x;
    if (idx >= n4) return;
    float4 v = *(const float4*)(src + idx * 4);
    uint2 hv, lv;
    cvt_hl4(v, hv, lv);
    *(uint2*)(H + idx * 4) = hv;
    *(uint2*)(L + idx * 4) = lv;
}

// ---------------- W [Krows, H] -> Wt hi/lo [H, Krows] ----------------
__global__ void transpose_w(const float* __restrict__ W,
                            __nv_bfloat16* __restrict__ Th, __nv_bfloat16* __restrict__ Tl,
                            int outLd) {
    __shared__ float s[32][33];
    int n0 = blockIdx.x * 32;
    int k0 = blockIdx.y * 32;
    int tx = threadIdx.x & 31, ty = threadIdx.x >> 5;
#pragma unroll
    for (int i = 0; i < 4; i++)
        s[ty + 8 * i][tx] = W[(long)(k0 + ty + 8 * i) * cH + n0 + tx];
    __syncthreads();
#pragma unroll
    for (int i = 0; i < 4; i++) {
        float v = s[tx][ty + 8 * i];
        __nv_bfloat16 h = __float2bfloat16(v);
        __nv_bfloat16 l = __float2bfloat16(v - __bfloat162float(h));
        long o = (long)(n0 + ty + 8 * i) * outLd + k0 + tx;
        Th[o] = h; Tl[o] = l;
    }
}

// ---------------- ft @ W1_top partials ----------------
__global__ void ft_contrib(const float* __restrict__ ft, const float* __restrict__ W1,
                           float* __restrict__ Hbp) {
    __shared__ float sf[cB * 64];
    int jx = blockIdx.x * 128 + threadIdx.x;
    int s = blockIdx.y;
    int k0 = s * 64;
    for (int i = threadIdx.x; i < cB * 64; i += 128) {
        int b = i >> 6, k = i & 63;
        sf[i] = ft[(long)b * cD + k0 + k];
    }
    __syncthreads();
    float acc[cB];
#pragma unroll
    for (int b = 0; b < cB; b++) acc[b] = 0.f;
#pragma unroll
    for (int kk = 0; kk < 64; kk += 8) {
        float wv[8];
#pragma unroll
        for (int u = 0; u < 8; u++)
            wv[u] = W1[(long)(k0 + kk + u) * cH + jx];
#pragma unroll
        for (int u = 0; u < 8; u++)
#pragma unroll
            for (int b = 0; b < cB; b++) acc[b] += sf[b * 64 + kk + u] * wv[u];
    }
#pragma unroll
    for (int b = 0; b < cB; b++)
        Hbp[(long)s * cB * cH + (long)b * cH + jx] = acc[b];
}

__global__ void ft_sum(const float* __restrict__ Hbp, float* __restrict__ Hbs) {
    int idx = blockIdx.x * 256 + threadIdx.x;
    if (idx >= cB * cH) return;
    float s = 0.f;
#pragma unroll
    for (int p = 0; p < FT_SPLIT; p++) s += Hbp[(long)p * cB * cH + idx];
    Hbs[idx] = s;
}

__global__ void tproj_reduce(const float* __restrict__ P, float* __restrict__ tp) {
    if (g_flag == 0) return;
    long idx = (long)blockIdx.x * blockDim.x + threadIdx.x;
    const long n4 = (long)cB * cX * cD / 4;
    if (idx >= n4) return;
    float4 a = *(const float4*)(P + idx * 4);
    float4 b = *(const float4*)(P + n4 * 4 + idx * 4);
    *(float4*)(&tp[idx * 4]) = make_float4(a.x + b.x, a.y + b.y, a.z + b.z, a.w + b.w);
}

// ---------------- MLP tail (rowBase for group pipelining) ----------------
__global__ void mlp_reduce(const float* __restrict__ Hp, const float* __restrict__ b1,
                           const float* __restrict__ W2, const float* __restrict__ b2,
                           float* __restrict__ scores, int accumulate,
                           const float* __restrict__ Hb, int rowBase) {
    int row = rowBase + blockIdx.x;
    int b = row >> 5;
    int tid = threadIdx.x;
    float s = 0.f;
    for (int j = tid; j < cH; j += 256) {
        float h = b1[j];
#pragma unroll
        for (int p = 0; p < MLP_SPLIT; p++) h += Hp[(long)p * ROWS * cH + (long)row * cH + j];
        if (Hb) h += Hb[(long)b * cH + j];
        h = fmaxf(h, 0.f);
        s += h * W2[j];
    }
    __shared__ float red[256];
    red[tid] = s;
    __syncthreads();
    for (int o = 128; o > 0; o >>= 1) {
        if (tid < o) red[tid] += red[tid + o];
        __syncthreads();
    }
    if (tid == 0) {
        float v = red[0] + b2[0];
        if (accumulate) scores[row] += v;
        else scores[row] = v;
    }
}

// ---------------- attention pooling per (b,i) -> X2 bf16 hi/lo (float4) ----------------
__global__ void attn_kernel(const float* __restrict__ inners,
                            const int* __restrict__ mt, const int* __restrict__ md,
                            const float* __restrict__ att_t, const float* __restrict__ att_d,
                            __nv_bfloat16* __restrict__ X2h, __nv_bfloat16* __restrict__ X2l,
                            int biBase) {
    int bi = biBase + blockIdx.x;
    int b = bi >> 5;
    int i = bi & 31;
    __shared__ float S[cX][cX];
    __shared__ float tw[cX], dw[cX];
    int tid = threadIdx.x;
    const long PS = (long)cB * cN * cX * 64;

    for (int idx = tid; idx < cX * cX; idx += 256) {
        int x = idx / cX, y = idx % cX;
        long o = ((long)b * (cN * cX) + i * cX + y) * 64 + x;
        float v = 0.f;
#pragma unroll
        for (int p = 0; p < INN_SPLIT; p++) v += inners[p * PS + o];
        int mm = mt[b * cX + x] * md[(b * cN + i) * cX + y];
        S[x][y] = (mm > 0) ? v : BIG_NEG_F;
    }
    __syncthreads();

    if (tid < cX) {
        float mx = -3.4e38f;
        for (int y = 0; y < cX; y++) mx = fmaxf(mx, S[tid][y]);
        tw[tid] = mx;
    } else if (tid < 2 * cX) {
        int y = tid - cX;
        float mx = -3.4e38f;
        for (int x = 0; x < cX; x++) mx = fmaxf(mx, S[x][y]);
        dw[y] = mx;
    }
    __syncthreads();

    if (tid == 0) {
        float m = -3.4e38f;
        for (int x = 0; x < cX; x++) m = fmaxf(m, tw[x]);
        float s = 0.f;
        for (int x = 0; x < cX; x++) { float e = expf(tw[x] - m); tw[x] = e; s += e; }
        float inv = 1.f / s;
        for (int x = 0; x < cX; x++) tw[x] *= inv;
    }
    if (tid == 32) {
        float m = -3.4e38f;
        for (int y = 0; y < cX; y++) m = fmaxf(m, dw[y]);
        float s = 0.f;
        for (int y = 0; y < cX; y++) { float e = expf(dw[y] - m); dw[y] = e; s += e; }
        float inv = 1.f / s;
        for (int y = 0; y < cX; y++) dw[y] *= inv;
    }
    __syncthreads();

    const float* tb = att_t + (long)b * cX * cD;
    const float* db = att_d + (long)(b * cN + i) * cX * cD;
    // float4-vectorized pooling: each thread handles 4 contiguous d's.
    for (int d0 = tid * 4; d0 < cD; d0 += 1024) {
        float4 tf = make_float4(0.f, 0.f, 0.f, 0.f);
        float4 df = make_float4(0.f, 0.f, 0.f, 0.f);
#pragma unroll
        for (int x = 0; x < cX; x++) {
            float wt = tw[x], wd = dw[x];
            float4 tv = *(const float4*)(tb + (long)x * cD + d0);
            float4 dv = *(const float4*)(db + (long)x * cD + d0);
            tf.x += wt * tv.x; tf.y += wt * tv.y; tf.z += wt * tv.z; tf.w += wt * tv.w;
            df.x += wd * dv.x; df.y += wd * dv.y; df.z += wd * dv.z; df.w += wd * dv.w;
        }
        uint2 thv, tlv, dhv, dlv;
        cvt_hl4(tf, thv, tlv);
        cvt_hl4(df, dhv, dlv);
        long o = (long)bi * K2 + d0;
        *(uint2*)(X2h + o) = thv;
        *(uint2*)(X2l + o) = tlv;
        *(uint2*)(X2h + o + cD) = dhv;
        *(uint2*)(X2l + o + cD) = dlv;
    }
}

// ---------------- final log_softmax ----------------
__global__ void logsoftmax_kernel(const float* __restrict__ scores, float* __restrict__ out) {
    int b = blockIdx.x;
    int n = threadIdx.x;
    float v = scores[b * cN + n];
    float m = v;
    for (int o = 16; o > 0; o >>= 1) m = fmaxf(m, __shfl_xor_sync(0xffffffffu, m, o));
    float e = expf(v - m);
    float s = e;
    for (int o = 16; o > 0; o >>= 1) s += __shfl_xor_sync(0xffffffffu, s, o);
    out[b * cN + n] = v - m - logf(s);
}

// ---------------- host ----------------
extern "C" void kernel_launch(void* const* d_in, const int* in_sizes, int n_in,
                              void* d_out, int out_size) {
    const float* fc_t = (const float*)d_in[0];
    const float* fc_d = (const float*)d_in[1];
    const float* att_t = (const float*)d_in[2];
    const float* att_d = (const float*)d_in[3];
    const int* am_t = (const int*)d_in[4];
    const int* am_d = (const int*)d_in[5];
    const float* W1 = (const float*)d_in[6];
    const float* b1 = (const float*)d_in[7];
    const float* W2 = (const float*)d_in[8];
    const float* b2 = (const float*)d_in[9];
    const float* Wbil = (const float*)d_in[10];
    const float* oW1 = (const float*)d_in[11];
    const float* ob1 = (const float*)d_in[12];
    const float* oW2 = (const float*)d_in[13];
    const float* ob2 = (const float*)d_in[14];
    float* out = (float*)d_out;

    float *Hp, *Hb, *Hbs, *tproj, *tprojP, *inn, *scores;
    __nv_bfloat16 *fdh, *fdl, *X2h, *X2l, *Wt1h, *Wt1l, *Wt2h, *Wt2l;
    cudaGetSymbolAddress((void**)&Hp, g_Hpart);
    cudaGetSymbolAddress((void**)&Hb, g_Hb);
    cudaGetSymbolAddress((void**)&Hbs, g_Hbs);
    cudaGetSymbolAddress((void**)&tproj, g_tproj);
    cudaGetSymbolAddress((void**)&tprojP, g_tprojP);
    cudaGetSymbolAddress((void**)&inn, g_inners);
    cudaGetSymbolAddress((void**)&scores, g_scores);
    cudaGetSymbolAddress((void**)&fdh, g_fdh);
    cudaGetSymbolAddress((void**)&fdl, g_fdl);
    cudaGetSymbolAddress((void**)&X2h, g_X2h);
    cudaGetSymbolAddress((void**)&X2l, g_X2l);
    cudaGetSymbolAddress((void**)&Wt1h, g_Wt1h);
    cudaGetSymbolAddress((void**)&Wt1l, g_Wt1l);
    cudaGetSymbolAddress((void**)&Wt2h, g_Wt2h);
    cudaGetSymbolAddress((void**)&Wt2l, g_Wt2l);

    static cudaStream_t s1 = nullptr, s2 = nullptr;
    static cudaEvent_t evFork = nullptr, evJoin = nullptr, evTp = nullptr, evG1 = nullptr;
    if (s1 == nullptr) {
        cudaStreamCreateWithFlags(&s1, cudaStreamNonBlocking);
        cudaStreamCreateWithFlags(&s2, cudaStreamNonBlocking);
        cudaEventCreateWithFlags(&evFork, cudaEventDisableTiming);
        cudaEventCreateWithFlags(&evJoin, cudaEventDisableTiming);
        cudaEventCreateWithFlags(&evTp, cudaEventDisableTiming);
        cudaEventCreateWithFlags(&evG1, cudaEventDisableTiming);
        cudaFuncSetAttribute((const void*)hgemm<0, 0>, cudaFuncAttributeMaxDynamicSharedMemorySize, SMEM_BYTES);
        cudaFuncSetAttribute((const void*)hgemm<0, 2>, cudaFuncAttributeMaxDynamicSharedMemorySize, SMEM_BYTES);
        cudaFuncSetAttribute((const void*)hgemm<1, 1>, cudaFuncAttributeMaxDynamicSharedMemorySize, SMEM_BYTES);
    }

    // ---- fork: stream1 runs the independent base-score chain ----
    cudaEventRecord(evFork, 0);
    cudaStreamWaitEvent(s1, evFork, 0);
    cudaStreamWaitEvent(s2, evFork, 0);

    // [stream1] base-score chain + oW1 transpose
    conv_split<<<(ROWS * cD / 4 + 255) / 256, 256, 0, s1>>>(fc_d, fdh, fdl, (long)ROWS * cD / 4);
    transpose_w<<<dim3(cH / 32, cD / 32), 256, 0, s1>>>(W1 + (long)cD * cH, Wt1h, Wt1l, cD);
    transpose_w<<<dim3(cH / 32, K2 / 32), 256, 0, s1>>>(oW1, Wt2h, Wt2l, K2);
    ft_contrib<<<dim3(cH / 128, FT_SPLIT), 128, 0, s1>>>(fc_t, W1, Hb);
    ft_sum<<<(cB * cH + 255) / 256, 256, 0, s1>>>(Hb, Hbs);
    hgemm<1, 1><<<dim3(cH / 64, ROWS / 128, MLP_SPLIT), 256, SMEM_BYTES, s1>>>(
        nullptr, fdh, fdl, nullptr, nullptr, Wt1h, Wt1l, Hp,
        ROWS, cH, (cD / MLP_SPLIT) / 32, cD, cD, cH, MLP_SPLIT, 0,
        0, 0, 0, (long)(cD / MLP_SPLIT), (long)(cD / MLP_SPLIT), (long)ROWS * cH);
    mlp_reduce<<<ROWS, 256, 0, s1>>>(Hp, b1, W2, b2, scores, 0, Hbs, 0);
    cudaEventRecord(evJoin, s1);

    // [default stream] flag + tproj fallback (shared by all groups)
    init_flag_kernel<<<1, 1>>>();
    check_identity<<<(cD * cD / 4 + 255) / 256, 256>>>(Wbil);
    hgemm<0, 0><<<dim3(cD / 64, (cB * cX + 127) / 128, 2), 256, SMEM_BYTES>>>(
        att_t, nullptr, nullptr, Wbil, nullptr, nullptr, nullptr, tprojP,
        cB * cX, cD, (cD / 2) / 32, cD, cD, cD, 2, 1,
        0, 0, 0, (long)(cD / 2), (long)(cD / 2) * cD, (long)cB * cX * cD);
    tproj_reduce<<<(cB * cX * cD / 4 + 255) / 256, 256>>>(tprojP, tproj);
    cudaEventRecord(evTp, 0);
    cudaStreamWaitEvent(s2, evTp, 0);

    // ---- pipelined batch groups: even groups on default stream, odd on s2 ----
    const long AD_B = (long)cN * cX * cD;       // att_d per-batch stride
    const long TP_B = (long)cX * cD;            // tproj/att_t per-batch stride
    const long IN_B = (long)cN * cX * 64;       // inners per-batch stride
    for (int grp = 0; grp < NGRP; grp++) {
        cudaStream_t st = (grp & 1) ? s2 : (cudaStream_t)0;
        const long bo = (long)grp * GB;
        hgemm<0, 2><<<dim3(1, (cN * cX) / 128, GB * INN_SPLIT), 256, SMEM_BYTES, st>>>(
            att_d + bo * AD_B, nullptr, nullptr, tproj + bo * TP_B, att_t + bo * TP_B,
            nullptr, nullptr, inn + bo * IN_B,
            cN * cX, 64, (cD / INN_SPLIT) / 32, cD, cD, cX, INN_SPLIT, 0,
            AD_B, TP_B, IN_B,
            (long)(cD / INN_SPLIT), (long)(cD / INN_SPLIT), (long)cB * cN * cX * 64);
        attn_kernel<<<GB * cN, 256, 0, st>>>(inn, am_t, am_d, att_t, att_d, X2h, X2l,
                                             (int)(bo * cN));
        cudaStreamWaitEvent(st, evJoin, 0);
        hgemm<1, 1><<<dim3(cH / 64, (GB * cN) / 128, MLP_SPLIT), 256, SMEM_BYTES, st>>>(
            nullptr, X2h + bo * cN * K2, X2l + bo * cN * K2, nullptr, nullptr, Wt2h, Wt2l,
            Hp + bo * cN * cH,
            GB * cN, cH, (K2 / MLP_SPLIT) / 32, K2, K2, cH, MLP_SPLIT, 0,
            0, 0, 0, (long)(K2 / MLP_SPLIT), (long)(K2 / MLP_SPLIT), (long)ROWS * cH);
        mlp_reduce<<<GB * cN, 256, 0, st>>>(Hp, ob1, oW2, ob2, scores, 1, nullptr,
                                            (int)(bo * cN));
    }
    cudaEventRecord(evG1, s2);
    cudaStreamWaitEvent(0, evG1, 0);

    logsoftmax_kernel<<<cB, 32>>>(scores, out);
}